// round 1
// baseline (speedup 1.0000x reference)
#include <cuda_runtime.h>
#include <stdint.h>
#include <math.h>

#define NTOK 32768
#define BATCH 8
#define SEQ 4096
#define DDIM 1024
#define HDIM 2048
#define MAXK 64

// -------- scratch (no cudaMalloc allowed) --------
static __device__ float g_logits[NTOK];
static __device__ float g_mask[NTOK];
static __device__ int   g_ksel;

// -------- threefry2x32-20 (JAX semantics) --------
__host__ __device__ __forceinline__ void tf2x32(uint32_t k0, uint32_t k1,
                                                uint32_t x0, uint32_t x1,
                                                uint32_t* o0, uint32_t* o1) {
  uint32_t ks2 = k0 ^ k1 ^ 0x1BD11BDAu;
#define ROTL(v, d) (((v) << (d)) | ((v) >> (32 - (d))))
#define RND(r) { x0 += x1; x1 = ROTL(x1, r); x1 ^= x0; }
  x0 += k0; x1 += k1;
  RND(13) RND(15) RND(26) RND(6)
  x0 += k1; x1 += ks2 + 1u;
  RND(17) RND(29) RND(16) RND(24)
  x0 += ks2; x1 += k0 + 2u;
  RND(13) RND(15) RND(26) RND(6)
  x0 += k0; x1 += k1 + 3u;
  RND(17) RND(29) RND(16) RND(24)
  x0 += k1; x1 += ks2 + 4u;
  RND(13) RND(15) RND(26) RND(6)
  x0 += ks2; x1 += k0 + 5u;
#undef RND
#undef ROTL
  *o0 = x0; *o1 = x1;
}

// partitionable 32-bit random bits: counter = (0, idx), output = x0 ^ x1
__device__ __forceinline__ float gumbel_at(uint32_t k0, uint32_t k1, uint32_t idx) {
  uint32_t a, b;
  tf2x32(k0, k1, 0u, idx, &a, &b);
  uint32_t bits = a ^ b;
  // jax.random.uniform(minval=1e-8, maxval=1-1e-8): span rounds to 1.0f in f32
  float u = __uint_as_float((bits >> 9) | 0x3f800000u) - 1.0f;
  u = u + 1e-8f;
  u = fmaxf(1e-8f, u);
  return -logf(-logf(u));
}

// -------- K0a: zero logits --------
__global__ void zero_logits_kernel() {
  int i = blockIdx.x * blockDim.x + threadIdx.x;
  if (i < NTOK) g_logits[i] = 0.0f;
}

// -------- K0b: learnable-k branch (64 values) --------
__global__ void k_select_kernel(const float* __restrict__ k_logits,
                                float* __restrict__ out_ek,
                                uint32_t r1k0, uint32_t r1k1) {
  __shared__ float z[MAXK];
  int t = threadIdx.x;  // 64 threads
  if (t < MAXK) {
    float g = gumbel_at(r1k0, r1k1, (uint32_t)t);
    z[t] = k_logits[t] + g;   // K_TAU = 1.0
  }
  __syncthreads();
  if (t == 0) {
    float m = -INFINITY; int am = 0;
    for (int i = 0; i < MAXK; i++) if (z[i] > m) { m = z[i]; am = i; }
    float s = 0.0f;
    float e[MAXK];
    for (int i = 0; i < MAXK; i++) { e[i] = expf(z[i] - m); s += e[i]; }
    float ek = 0.0f;
    for (int i = 0; i < MAXK; i++) ek += (e[i] / s) * (float)(i + 1);
    out_ek[0] = ek;
    g_ksel = am + 1;
  }
}

// -------- K1: fused fp32 MLP -> importance logits --------
// logit[t] = sum_j relu(sum_k X[t,k]*W1[k,j] + b1[j]) * W2[j]
// BM=128 tokens per block-row, grid.y splits H into 2 halves of 1024.
// Per n-tile (BN=64): full K loop, then relu+W2 epilogue folded into lacc.
#define BM 128
#define BN 64
#define BK 16
__global__ __launch_bounds__(256, 2)
void mlp_logits_kernel(const float* __restrict__ X,
                       const float* __restrict__ W1,
                       const float* __restrict__ b1,
                       const float* __restrict__ W2) {
  __shared__ float As[BK][BM];
  __shared__ float Bs[BK][BN];
  __shared__ float Red[16][BM];

  const int tid = threadIdx.x;
  const int tx = tid & 15;      // column group (4 cols)
  const int ty = tid >> 4;      // row group (8 rows)
  const int row0 = blockIdx.x * BM;
  const int nbase = blockIdx.y * (HDIM / 2);

  float lacc[8];
#pragma unroll
  for (int i = 0; i < 8; i++) lacc[i] = 0.0f;

  for (int n0 = nbase; n0 < nbase + HDIM / 2; n0 += BN) {
    float c[8][4];
#pragma unroll
    for (int i = 0; i < 8; i++)
#pragma unroll
      for (int j = 0; j < 4; j++) c[i][j] = 0.0f;

    for (int k0 = 0; k0 < DDIM; k0 += BK) {
      __syncthreads();
      // load A tile: 128 rows x 16 k  (512 float4, 2 per thread)
#pragma unroll
      for (int p = 0; p < 2; p++) {
        int f = tid + p * 256;
        int r = f >> 2;
        int c4 = (f & 3) * 4;
        float4 v = *(const float4*)&X[(size_t)(row0 + r) * DDIM + k0 + c4];
        As[c4 + 0][r] = v.x; As[c4 + 1][r] = v.y;
        As[c4 + 2][r] = v.z; As[c4 + 3][r] = v.w;
      }
      // load B tile: 16 k x 64 n (one float4 per thread)
      {
        int kk = tid >> 4;
        int j = (tid & 15) * 4;
        float4 v = *(const float4*)&W1[(size_t)(k0 + kk) * HDIM + n0 + j];
        *(float4*)&Bs[kk][j] = v;
      }
      __syncthreads();
#pragma unroll
      for (int kk = 0; kk < BK; kk++) {
        float4 a0 = *(const float4*)&As[kk][ty * 8];
        float4 a1 = *(const float4*)&As[kk][ty * 8 + 4];
        float4 bv = *(const float4*)&Bs[kk][tx * 4];
        float av[8] = {a0.x, a0.y, a0.z, a0.w, a1.x, a1.y, a1.z, a1.w};
        float bb[4] = {bv.x, bv.y, bv.z, bv.w};
#pragma unroll
        for (int i = 0; i < 8; i++)
#pragma unroll
          for (int j = 0; j < 4; j++) c[i][j] = fmaf(av[i], bb[j], c[i][j]);
      }
    }
    // epilogue: bias, relu, weight by W2, accumulate per-token logit
    float4 b1v = *(const float4*)&b1[n0 + tx * 4];
    float4 w2v = *(const float4*)&W2[n0 + tx * 4];
    float bb[4] = {b1v.x, b1v.y, b1v.z, b1v.w};
    float ww[4] = {w2v.x, w2v.y, w2v.z, w2v.w};
#pragma unroll
    for (int i = 0; i < 8; i++)
#pragma unroll
      for (int j = 0; j < 4; j++) {
        float h = fmaxf(c[i][j] + bb[j], 0.0f);
        lacc[i] = fmaf(h, ww[j], lacc[i]);
      }
  }

  // reduce lacc across the 16 tx groups
  __syncthreads();
#pragma unroll
  for (int i = 0; i < 8; i++) Red[tx][ty * 8 + i] = lacc[i];
  __syncthreads();
  if (tid < BM) {
    float s = 0.0f;
#pragma unroll
    for (int x = 0; x < 16; x++) s += Red[x][tid];
    // exactly 2 atomic addends per address (grid.y==2): commutative -> deterministic
    atomicAdd(&g_logits[row0 + tid], s);
  }
}

// -------- K2: per-row gumbel perturb + iterative top-k --------
__global__ __launch_bounds__(256)
void topk_kernel(const float* __restrict__ b2,
                 float* __restrict__ out_mask,
                 uint32_t r2k0, uint32_t r2k1) {
  __shared__ float vals[SEQ];
  __shared__ unsigned char ms[SEQ];
  __shared__ float rv[256];
  __shared__ int ri[256];

  const int row = blockIdx.x;   // 0..7
  const int tid = threadIdx.x;  // 256 threads
  const float bias2 = b2[0];

  for (int i = tid; i < SEQ; i += 256) {
    uint32_t idx = (uint32_t)(row * SEQ + i);
    vals[i] = g_logits[idx] + bias2 + gumbel_at(r2k0, r2k1, idx);
    ms[i] = 0;
  }
  __syncthreads();

  const int k = g_ksel;
  for (int it = 0; it < k; it++) {
    float best = -INFINITY; int bi = SEQ;
    for (int i = tid; i < SEQ; i += 256) {
      float v = vals[i];
      if (v > best || (v == best && i < bi)) { best = v; bi = i; }
    }
    rv[tid] = best; ri[tid] = bi;
    __syncthreads();
    for (int s = 128; s > 0; s >>= 1) {
      if (tid < s) {
        if (rv[tid + s] > rv[tid] ||
            (rv[tid + s] == rv[tid] && ri[tid + s] < ri[tid])) {
          rv[tid] = rv[tid + s]; ri[tid] = ri[tid + s];
        }
      }
      __syncthreads();
    }
    if (tid == 0) { vals[ri[0]] = -INFINITY; ms[ri[0]] = 1; }
    __syncthreads();
  }

  for (int i = tid; i < SEQ; i += 256) {
    float m = (float)ms[i];
    out_mask[row * SEQ + i] = m;
    g_mask[row * SEQ + i] = m;
  }
}

// -------- K3: masked scatter of embeddings --------
__global__ __launch_bounds__(256)
void scatter_kernel(const float* __restrict__ X, float* __restrict__ out) {
  const int t = blockIdx.x;          // token
  const int tid = threadIdx.x;       // 256 threads x float4 = 1024 floats
  const float m = g_mask[t];
  float4* dst = (float4*)(out + (size_t)t * DDIM);
  if (m != 0.0f) {
    const float4* src = (const float4*)(X + (size_t)t * DDIM);
    dst[tid] = src[tid];
  } else {
    dst[tid] = make_float4(0.0f, 0.0f, 0.0f, 0.0f);
  }
}

// -------- launch --------
extern "C" void kernel_launch(void* const* d_in, const int* in_sizes, int n_in,
                              void* d_out, int out_size) {
  const float* X  = (const float*)d_in[0];   // [8,4096,1024]
  const float* W1 = (const float*)d_in[1];   // [1024,2048]
  const float* b1 = (const float*)d_in[2];   // [2048]
  const float* W2 = (const float*)d_in[3];   // [2048,1]
  const float* b2 = (const float*)d_in[4];   // [1]
  const float* kl = (const float*)d_in[5];   // [64]

  float* out = (float*)d_out;
  float* out_mask = out + (size_t)NTOK * DDIM;   // 33554432
  float* out_ek   = out_mask + NTOK;             // +32768

  // jax.random.key(42) -> (0,42); partitionable split: keys[i] = threefry(key,(0,i))
  uint32_t r1k0, r1k1, r2k0, r2k1;
  tf2x32(0u, 42u, 0u, 0u, &r1k0, &r1k1);
  tf2x32(0u, 42u, 0u, 1u, &r2k0, &r2k1);

  zero_logits_kernel<<<NTOK / 256, 256>>>();
  k_select_kernel<<<1, 64>>>(kl, out_ek, r1k0, r1k1);
  mlp_logits_kernel<<<dim3(NTOK / BM, 2), 256>>>(X, W1, b1, W2);
  topk_kernel<<<BATCH, 256>>>(b2, out_mask, r2k0, r2k1);
  scatter_kernel<<<NTOK, 256>>>(X, out);
}

// round 3
// speedup vs baseline: 2.3719x; 2.3719x over previous
#include <cuda_runtime.h>
#include <cuda_bf16.h>
#include <stdint.h>
#include <math.h>

#define NTOK 32768
#define BATCH 8
#define SEQ 4096
#define DDIM 1024
#define HDIM 2048
#define MAXK 64

#define BM 128
#define BN 128
#define BK 32
#define NCHUNKS (HDIM / BN)     // 16
#define KSTAGES (DDIM / BK)     // 32
#define NSTAGES (NCHUNKS * KSTAGES)  // 512

// smem byte layout (dynamic)
#define STAGE_BYTES 40960   // [Ahi 10240][Alo 10240][Bhi 10240][Blo 10240], row stride 80B
#define B1S_OFF  81920
#define W2S_OFF  90112
#define RED_OFF  98304
#define DYN_SMEM 99328

// ---------------- scratch ----------------
static __device__ float g_logits[NTOK];
static __device__ float g_mask[NTOK];
static __device__ int   g_ksel;
static __device__ __nv_bfloat16 g_Xhi[(size_t)NTOK * DDIM];
static __device__ __nv_bfloat16 g_Xlo[(size_t)NTOK * DDIM];
static __device__ __nv_bfloat16 g_Whi[(size_t)HDIM * DDIM];  // n-major (transposed)
static __device__ __nv_bfloat16 g_Wlo[(size_t)HDIM * DDIM];

// ---------------- PTX helpers ----------------
__device__ __forceinline__ uint32_t smem_u32(const void* p) {
  uint32_t a;
  asm("{ .reg .u64 t; cvta.to.shared.u64 t, %1; cvt.u32.u64 %0, t; }" : "=r"(a) : "l"(p));
  return a;
}
__device__ __forceinline__ void cp16(uint32_t saddr, const void* gaddr) {
  asm volatile("cp.async.cg.shared.global [%0], [%1], 16;" :: "r"(saddr), "l"(gaddr));
}
#define CP_COMMIT() asm volatile("cp.async.commit_group;" ::: "memory")
#define CP_WAIT1()  asm volatile("cp.async.wait_group 1;" ::: "memory")
#define CP_WAIT0()  asm volatile("cp.async.wait_group 0;" ::: "memory")

__device__ __forceinline__ void ldsm4(uint32_t* r, uint32_t addr) {
  asm volatile("ldmatrix.sync.aligned.m8n8.x4.shared.b16 {%0,%1,%2,%3}, [%4];"
               : "=r"(r[0]), "=r"(r[1]), "=r"(r[2]), "=r"(r[3]) : "r"(addr));
}
__device__ __forceinline__ void mma16816(float* c, const uint32_t* a, const uint32_t* b) {
  asm volatile("mma.sync.aligned.m16n8k16.row.col.f32.bf16.bf16.f32 "
               "{%0,%1,%2,%3}, {%4,%5,%6,%7}, {%8,%9}, {%0,%1,%2,%3};"
               : "+f"(c[0]), "+f"(c[1]), "+f"(c[2]), "+f"(c[3])
               : "r"(a[0]), "r"(a[1]), "r"(a[2]), "r"(a[3]), "r"(b[0]), "r"(b[1]));
}

// ---------------- threefry2x32-20 (JAX) ----------------
__host__ __device__ __forceinline__ void tf2x32(uint32_t k0, uint32_t k1,
                                                uint32_t x0, uint32_t x1,
                                                uint32_t* o0, uint32_t* o1) {
  uint32_t ks2 = k0 ^ k1 ^ 0x1BD11BDAu;
#define ROTL(v, d) (((v) << (d)) | ((v) >> (32 - (d))))
#define RND(r) { x0 += x1; x1 = ROTL(x1, r); x1 ^= x0; }
  x0 += k0; x1 += k1;
  RND(13) RND(15) RND(26) RND(6)
  x0 += k1; x1 += ks2 + 1u;
  RND(17) RND(29) RND(16) RND(24)
  x0 += ks2; x1 += k0 + 2u;
  RND(13) RND(15) RND(26) RND(6)
  x0 += k0; x1 += k1 + 3u;
  RND(17) RND(29) RND(16) RND(24)
  x0 += k1; x1 += ks2 + 4u;
  RND(13) RND(15) RND(26) RND(6)
  x0 += ks2; x1 += k0 + 5u;
#undef RND
#undef ROTL
  *o0 = x0; *o1 = x1;
}
__device__ __forceinline__ float gumbel_at(uint32_t k0, uint32_t k1, uint32_t idx) {
  uint32_t a, b;
  tf2x32(k0, k1, 0u, idx, &a, &b);
  uint32_t bits = a ^ b;
  float u = __uint_as_float((bits >> 9) | 0x3f800000u) - 1.0f;
  u = u + 1e-8f;
  u = fmaxf(1e-8f, u);
  return -logf(-logf(u));
}

// ---------------- conversion kernels ----------------
__global__ __launch_bounds__(256) void convX_kernel(const float* __restrict__ X) {
  size_t i = (size_t)blockIdx.x * 256 + threadIdx.x;   // float4 index
  float4 v = ((const float4*)X)[i];
  __nv_bfloat16 h0 = __float2bfloat16(v.x), h1 = __float2bfloat16(v.y);
  __nv_bfloat16 h2 = __float2bfloat16(v.z), h3 = __float2bfloat16(v.w);
  __nv_bfloat16 l0 = __float2bfloat16(v.x - __bfloat162float(h0));
  __nv_bfloat16 l1 = __float2bfloat16(v.y - __bfloat162float(h1));
  __nv_bfloat16 l2 = __float2bfloat16(v.z - __bfloat162float(h2));
  __nv_bfloat16 l3 = __float2bfloat16(v.w - __bfloat162float(h3));
  __nv_bfloat162* H = (__nv_bfloat162*)g_Xhi;
  __nv_bfloat162* L = (__nv_bfloat162*)g_Xlo;
  H[i * 2] = __nv_bfloat162(h0, h1); H[i * 2 + 1] = __nv_bfloat162(h2, h3);
  L[i * 2] = __nv_bfloat162(l0, l1); L[i * 2 + 1] = __nv_bfloat162(l2, l3);
}

__global__ __launch_bounds__(256) void convW_kernel(const float* __restrict__ W1) {
  __shared__ float s[32][33];
  int n0 = blockIdx.x * 32;
  int k0 = blockIdx.y * 32;
  int tx = threadIdx.x & 31, ty = threadIdx.x >> 5;   // ty 0..7
#pragma unroll
  for (int j = 0; j < 4; j++) {
    int k = k0 + ty + j * 8;
    s[ty + j * 8][tx] = W1[(size_t)k * HDIM + n0 + tx];
  }
  __syncthreads();
#pragma unroll
  for (int j = 0; j < 4; j++) {
    int n = n0 + ty + j * 8;
    float v = s[tx][ty + j * 8];
    __nv_bfloat16 h = __float2bfloat16(v);
    __nv_bfloat16 l = __float2bfloat16(v - __bfloat162float(h));
    g_Whi[(size_t)n * DDIM + k0 + tx] = h;
    g_Wlo[(size_t)n * DDIM + k0 + tx] = l;
  }
}

// ---------------- k-select ----------------
__global__ void k_select_kernel(const float* __restrict__ k_logits,
                                float* __restrict__ out_ek,
                                uint32_t r1k0, uint32_t r1k1) {
  __shared__ float z[MAXK];
  int t = threadIdx.x;
  if (t < MAXK) z[t] = k_logits[t] + gumbel_at(r1k0, r1k1, (uint32_t)t);
  __syncthreads();
  if (t == 0) {
    float m = -INFINITY; int am = 0;
    for (int i = 0; i < MAXK; i++) if (z[i] > m) { m = z[i]; am = i; }
    float s = 0.0f, e[MAXK];
    for (int i = 0; i < MAXK; i++) { e[i] = expf(z[i] - m); s += e[i]; }
    float ek = 0.0f;
    for (int i = 0; i < MAXK; i++) ek += (e[i] / s) * (float)(i + 1);
    out_ek[0] = ek;
    g_ksel = am + 1;
  }
}

// ---------------- fused HMMA GEMM -> logits ----------------
// C[128 tok x 2048 h] = Xhi@Whi + Xhi@Wlo + Xlo@Whi (bf16 mma, fp32 accum),
// fused epilogue per 128-col chunk: relu(C+b1)*W2 summed into per-row logit.
__device__ __forceinline__ void issue_stage(uint32_t sbase, int buf, int row0,
                                            int nb, int k0, int tid) {
  const uint32_t stg = sbase + buf * STAGE_BYTES;
#pragma unroll
  for (int i = 0; i < 8; i++) {
    int c = tid + i * 256;
    int seg = c >> 9;          // 0:Ahi 1:Alo 2:Bhi 3:Blo  (warp-uniform)
    int cc = c & 511;
    int row = cc >> 2, half = cc & 3;
    const __nv_bfloat16* g;
    int grow;
    if (seg == 0)      { g = g_Xhi; grow = row0 + row; }
    else if (seg == 1) { g = g_Xlo; grow = row0 + row; }
    else if (seg == 2) { g = g_Whi; grow = nb + row; }
    else               { g = g_Wlo; grow = nb + row; }
    const void* gp = (const void*)(g + (((size_t)grow) << 10) + k0 + half * 8);
    uint32_t sp = stg + seg * 10240 + row * 80 + half * 16;
    cp16(sp, gp);
  }
}

__global__ __launch_bounds__(256, 1)
void gemm_logits_kernel(const float* __restrict__ b1, const float* __restrict__ W2) {
  extern __shared__ char smem[];
  const uint32_t sb = smem_u32(smem);
  const int tid = threadIdx.x;
  const int lane = tid & 31;
  const int wid = tid >> 5;
  const int wm = wid >> 1;          // 0..3  (m)
  const int wn = wid & 1;           // 0..1  (n)
  const int row0 = blockIdx.x * BM;

  float* b1s = (float*)(smem + B1S_OFF);
  float* w2s = (float*)(smem + W2S_OFF);
  float* red = (float*)(smem + RED_OFF);

  // prefetch stage 0
  issue_stage(sb, 0, row0, 0, 0, tid);
  CP_COMMIT();

  // stage b1 / W2
#pragma unroll
  for (int i = 0; i < 8; i++) {
    b1s[tid + i * 256] = b1[tid + i * 256];
    w2s[tid + i * 256] = W2[tid + i * 256];
  }

  float C[2][8][4];
#pragma unroll
  for (int mi = 0; mi < 2; mi++)
#pragma unroll
    for (int ni = 0; ni < 8; ni++)
#pragma unroll
      for (int j = 0; j < 4; j++) C[mi][ni][j] = 0.0f;
  float lacc[4] = {0.0f, 0.0f, 0.0f, 0.0f};

  const int lr = lane & 15, lh = lane >> 4;

  for (int s = 0; s < NSTAGES; s++) {
    const int buf = s & 1;
    if (s + 1 < NSTAGES) {
      int s1 = s + 1;
      issue_stage(sb, s1 & 1, row0, (s1 >> 5) * BN, (s1 & 31) * BK, tid);
      CP_COMMIT();
      CP_WAIT1();
    } else {
      CP_WAIT0();
    }
    __syncthreads();

    // compute current stage
    const uint32_t stg = sb + buf * STAGE_BYTES;
    const uint32_t aB = stg + (wm * 32 + lr) * 80 + lh * 16;
    const uint32_t bB = stg + 20480 + (wn * 64 + lr) * 80 + lh * 16;
#pragma unroll
    for (int k16 = 0; k16 < 2; k16++) {
      uint32_t ah[2][4], al[2][4], bh[8][2], bl[8][2];
#pragma unroll
      for (int mi = 0; mi < 2; mi++) {
        ldsm4(ah[mi], aB + mi * (16 * 80) + k16 * 32);
        ldsm4(al[mi], aB + 10240 + mi * (16 * 80) + k16 * 32);
      }
#pragma unroll
      for (int nt2 = 0; nt2 < 4; nt2++) {
        uint32_t r[4];
        ldsm4(r, bB + nt2 * (16 * 80) + k16 * 32);
        bh[2 * nt2][0] = r[0]; bh[2 * nt2][1] = r[2];
        bh[2 * nt2 + 1][0] = r[1]; bh[2 * nt2 + 1][1] = r[3];
        ldsm4(r, bB + 10240 + nt2 * (16 * 80) + k16 * 32);
        bl[2 * nt2][0] = r[0]; bl[2 * nt2][1] = r[2];
        bl[2 * nt2 + 1][0] = r[1]; bl[2 * nt2 + 1][1] = r[3];
      }
#pragma unroll
      for (int mi = 0; mi < 2; mi++)
#pragma unroll
        for (int ni = 0; ni < 8; ni++) mma16816(C[mi][ni], ah[mi], bh[ni]);
#pragma unroll
      for (int mi = 0; mi < 2; mi++)
#pragma unroll
        for (int ni = 0; ni < 8; ni++) mma16816(C[mi][ni], ah[mi], bl[ni]);
#pragma unroll
      for (int mi = 0; mi < 2; mi++)
#pragma unroll
        for (int ni = 0; ni < 8; ni++) mma16816(C[mi][ni], al[mi], bh[ni]);
    }

    if ((s & 31) == 31) {
      // epilogue for n-chunk nc = s >> 5
      const int colbase = (s >> 5) * BN + wn * 64 + (lane & 3) * 2;
#pragma unroll
      for (int ni = 0; ni < 8; ni++) {
        const int c0 = colbase + ni * 8;
        const float b10 = b1s[c0], b11 = b1s[c0 + 1];
        const float w20 = w2s[c0], w21 = w2s[c0 + 1];
#pragma unroll
        for (int mi = 0; mi < 2; mi++) {
          lacc[mi * 2 + 0] += fmaxf(C[mi][ni][0] + b10, 0.0f) * w20
                            + fmaxf(C[mi][ni][1] + b11, 0.0f) * w21;
          lacc[mi * 2 + 1] += fmaxf(C[mi][ni][2] + b10, 0.0f) * w20
                            + fmaxf(C[mi][ni][3] + b11, 0.0f) * w21;
          C[mi][ni][0] = 0.0f; C[mi][ni][1] = 0.0f;
          C[mi][ni][2] = 0.0f; C[mi][ni][3] = 0.0f;
        }
      }
    }
    __syncthreads();
  }

  // reduce lacc over the quad (columns) -> full row partials per n-warp
#pragma unroll
  for (int j = 0; j < 4; j++) {
    lacc[j] += __shfl_xor_sync(0xFFFFFFFFu, lacc[j], 1);
    lacc[j] += __shfl_xor_sync(0xFFFFFFFFu, lacc[j], 2);
  }
  if ((lane & 3) == 0) {
    const int r = lane >> 2;
    red[wn * 128 + wm * 32 + r]      = lacc[0];
    red[wn * 128 + wm * 32 + 8 + r]  = lacc[1];
    red[wn * 128 + wm * 32 + 16 + r] = lacc[2];
    red[wn * 128 + wm * 32 + 24 + r] = lacc[3];
  }
  __syncthreads();
  if (tid < BM) g_logits[row0 + tid] = red[tid] + red[128 + tid];
}

// ---------------- top-k ----------------
__global__ __launch_bounds__(1024)
void topk_kernel(const float* __restrict__ b2, float* __restrict__ out_mask,
                 uint32_t r2k0, uint32_t r2k1) {
  __shared__ float vals[SEQ];
  __shared__ float msk[SEQ];
  __shared__ float wv[32];
  __shared__ int wi[32];
  const int row = blockIdx.x;
  const int tid = threadIdx.x;
  const int w = tid >> 5, l = tid & 31;
  const float bias2 = b2[0];

#pragma unroll
  for (int j = 0; j < 4; j++) {
    int i = tid + j * 1024;
    uint32_t idx = (uint32_t)(row * SEQ + i);
    vals[i] = g_logits[idx] + bias2 + gumbel_at(r2k0, r2k1, idx);
    msk[i] = 0.0f;
  }
  __syncthreads();

  const int k = g_ksel;
  for (int it = 0; it < k; it++) {
    float best = -INFINITY; int bi = SEQ;
#pragma unroll
    for (int j = 0; j < 4; j++) {
      int i = tid + j * 1024;
      float v = vals[i];
      if (v > best || (v == best && i < bi)) { best = v; bi = i; }
    }
#pragma unroll
    for (int off = 16; off > 0; off >>= 1) {
      float ov = __shfl_down_sync(0xFFFFFFFFu, best, off);
      int oi = __shfl_down_sync(0xFFFFFFFFu, bi, off);
      if (ov > best || (ov == best && oi < bi)) { best = ov; bi = oi; }
    }
    if (l == 0) { wv[w] = best; wi[w] = bi; }
    __syncthreads();
    if (tid < 32) {
      best = wv[tid]; bi = wi[tid];
#pragma unroll
      for (int off = 16; off > 0; off >>= 1) {
        float ov = __shfl_down_sync(0xFFFFFFFFu, best, off);
        int oi = __shfl_down_sync(0xFFFFFFFFu, bi, off);
        if (ov > best || (ov == best && oi < bi)) { best = ov; bi = oi; }
      }
      if (tid == 0) { vals[bi] = -INFINITY; msk[bi] = 1.0f; }
    }
    __syncthreads();
  }
#pragma unroll
  for (int j = 0; j < 4; j++) {
    int i = tid + j * 1024;
    float m = msk[i];
    out_mask[row * SEQ + i] = m;
    g_mask[row * SEQ + i] = m;
  }
}

// ---------------- scatter ----------------
__global__ __launch_bounds__(256)
void scatter_kernel(const float* __restrict__ X, float* __restrict__ out) {
  const int t = blockIdx.x;
  const int tid = threadIdx.x;
  const float m = g_mask[t];
  float4* dst = (float4*)(out + (size_t)t * DDIM);
  if (m != 0.0f) {
    const float4* src = (const float4*)(X + (size_t)t * DDIM);
    dst[tid] = src[tid];
  } else {
    dst[tid] = make_float4(0.0f, 0.0f, 0.0f, 0.0f);
  }
}

// ---------------- launch ----------------
extern "C" void kernel_launch(void* const* d_in, const int* in_sizes, int n_in,
                              void* d_out, int out_size) {
  const float* X  = (const float*)d_in[0];
  const float* W1 = (const float*)d_in[1];
  const float* b1 = (const float*)d_in[2];
  const float* W2 = (const float*)d_in[3];
  const float* b2 = (const float*)d_in[4];
  const float* kl = (const float*)d_in[5];

  float* out = (float*)d_out;
  float* out_mask = out + (size_t)NTOK * DDIM;
  float* out_ek   = out_mask + NTOK;

  uint32_t r1k0, r1k1, r2k0, r2k1;
  tf2x32(0u, 42u, 0u, 0u, &r1k0, &r1k1);
  tf2x32(0u, 42u, 0u, 1u, &r2k0, &r2k1);

  cudaFuncSetAttribute(gemm_logits_kernel,
                       cudaFuncAttributeMaxDynamicSharedMemorySize, DYN_SMEM);

  convX_kernel<<<(NTOK * DDIM / 4) / 256, 256>>>(X);
  convW_kernel<<<dim3(HDIM / 32, DDIM / 32), 256>>>(W1);
  k_select_kernel<<<1, 64>>>(kl, out_ek, r1k0, r1k1);
  gemm_logits_kernel<<<NTOK / BM, 256, DYN_SMEM>>>(b1, W2);
  topk_kernel<<<BATCH, 1024>>>(b2, out_mask, r2k0, r2k1);
  scatter_kernel<<<NTOK, 256>>>(X, out);
}

// round 4
// speedup vs baseline: 2.6708x; 1.1261x over previous
#include <cuda_runtime.h>
#include <cuda_bf16.h>
#include <stdint.h>
#include <math.h>

#define NTOK 32768
#define BATCH 8
#define SEQ 4096
#define DDIM 1024
#define HDIM 2048
#define MAXK 64

#define BM 128
#define BN 128
#define BK 32
#define NCHUNKS (HDIM / BN)     // 16
#define KSTAGES (DDIM / BK)     // 32
#define NSTAGES (NCHUNKS * KSTAGES)  // 512

// smem byte layout (dynamic)
#define STAGE_BYTES 40960   // [Ahi 10240][Alo 10240][Bhi 10240][Blo 10240], row stride 80B
#define B1S_OFF  81920
#define W2S_OFF  90112
#define RED_OFF  98304
#define DYN_SMEM 99328

// ---------------- scratch ----------------
static __device__ float g_logits[NTOK];
static __device__ float g_mask[NTOK];
static __device__ int   g_ksel;
static __device__ __nv_bfloat16 g_Xhi[(size_t)NTOK * DDIM];
static __device__ __nv_bfloat16 g_Xlo[(size_t)NTOK * DDIM];
static __device__ __nv_bfloat16 g_Whi[(size_t)HDIM * DDIM];  // n-major (transposed)
static __device__ __nv_bfloat16 g_Wlo[(size_t)HDIM * DDIM];

// ---------------- PTX helpers ----------------
__device__ __forceinline__ uint32_t smem_u32(const void* p) {
  uint32_t a;
  asm("{ .reg .u64 t; cvta.to.shared.u64 t, %1; cvt.u32.u64 %0, t; }" : "=r"(a) : "l"(p));
  return a;
}
__device__ __forceinline__ void cp16(uint32_t saddr, const void* gaddr) {
  asm volatile("cp.async.cg.shared.global [%0], [%1], 16;" :: "r"(saddr), "l"(gaddr));
}
#define CP_COMMIT() asm volatile("cp.async.commit_group;" ::: "memory")
#define CP_WAIT0()  asm volatile("cp.async.wait_group 0;" ::: "memory")

__device__ __forceinline__ void ldsm4(uint32_t* r, uint32_t addr) {
  asm volatile("ldmatrix.sync.aligned.m8n8.x4.shared.b16 {%0,%1,%2,%3}, [%4];"
               : "=r"(r[0]), "=r"(r[1]), "=r"(r[2]), "=r"(r[3]) : "r"(addr));
}
__device__ __forceinline__ void mma16816(float* c, const uint32_t* a, const uint32_t* b) {
  asm volatile("mma.sync.aligned.m16n8k16.row.col.f32.bf16.bf16.f32 "
               "{%0,%1,%2,%3}, {%4,%5,%6,%7}, {%8,%9}, {%0,%1,%2,%3};"
               : "+f"(c[0]), "+f"(c[1]), "+f"(c[2]), "+f"(c[3])
               : "r"(a[0]), "r"(a[1]), "r"(a[2]), "r"(a[3]), "r"(b[0]), "r"(b[1]));
}

// ---------------- threefry2x32-20 (JAX) ----------------
__host__ __device__ __forceinline__ void tf2x32(uint32_t k0, uint32_t k1,
                                                uint32_t x0, uint32_t x1,
                                                uint32_t* o0, uint32_t* o1) {
  uint32_t ks2 = k0 ^ k1 ^ 0x1BD11BDAu;
#define ROTL(v, d) (((v) << (d)) | ((v) >> (32 - (d))))
#define RND(r) { x0 += x1; x1 = ROTL(x1, r); x1 ^= x0; }
  x0 += k0; x1 += k1;
  RND(13) RND(15) RND(26) RND(6)
  x0 += k1; x1 += ks2 + 1u;
  RND(17) RND(29) RND(16) RND(24)
  x0 += ks2; x1 += k0 + 2u;
  RND(13) RND(15) RND(26) RND(6)
  x0 += k0; x1 += k1 + 3u;
  RND(17) RND(29) RND(16) RND(24)
  x0 += k1; x1 += ks2 + 4u;
  RND(13) RND(15) RND(26) RND(6)
  x0 += ks2; x1 += k0 + 5u;
#undef RND
#undef ROTL
  *o0 = x0; *o1 = x1;
}
__device__ __forceinline__ float gumbel_at(uint32_t k0, uint32_t k1, uint32_t idx) {
  uint32_t a, b;
  tf2x32(k0, k1, 0u, idx, &a, &b);
  uint32_t bits = a ^ b;
  float u = __uint_as_float((bits >> 9) | 0x3f800000u) - 1.0f;
  u = u + 1e-8f;
  u = fmaxf(1e-8f, u);
  return -logf(-logf(u));
}

// ---------------- conversion kernels ----------------
__global__ __launch_bounds__(256) void convX_kernel(const float* __restrict__ X) {
  size_t i = (size_t)blockIdx.x * 256 + threadIdx.x;   // float4 index
  float4 v = ((const float4*)X)[i];
  __nv_bfloat16 h0 = __float2bfloat16(v.x), h1 = __float2bfloat16(v.y);
  __nv_bfloat16 h2 = __float2bfloat16(v.z), h3 = __float2bfloat16(v.w);
  __nv_bfloat16 l0 = __float2bfloat16(v.x - __bfloat162float(h0));
  __nv_bfloat16 l1 = __float2bfloat16(v.y - __bfloat162float(h1));
  __nv_bfloat16 l2 = __float2bfloat16(v.z - __bfloat162float(h2));
  __nv_bfloat16 l3 = __float2bfloat16(v.w - __bfloat162float(h3));
  __nv_bfloat162* H = (__nv_bfloat162*)g_Xhi;
  __nv_bfloat162* L = (__nv_bfloat162*)g_Xlo;
  H[i * 2] = __nv_bfloat162(h0, h1); H[i * 2 + 1] = __nv_bfloat162(h2, h3);
  L[i * 2] = __nv_bfloat162(l0, l1); L[i * 2 + 1] = __nv_bfloat162(l2, l3);
}

__global__ __launch_bounds__(256) void convW_kernel(const float* __restrict__ W1) {
  __shared__ float s[32][33];
  int n0 = blockIdx.x * 32;
  int k0 = blockIdx.y * 32;
  int tx = threadIdx.x & 31, ty = threadIdx.x >> 5;   // ty 0..7
#pragma unroll
  for (int j = 0; j < 4; j++) {
    int k = k0 + ty + j * 8;
    s[ty + j * 8][tx] = W1[(size_t)k * HDIM + n0 + tx];
  }
  __syncthreads();
#pragma unroll
  for (int j = 0; j < 4; j++) {
    int n = n0 + ty + j * 8;
    float v = s[tx][ty + j * 8];
    __nv_bfloat16 h = __float2bfloat16(v);
    __nv_bfloat16 l = __float2bfloat16(v - __bfloat162float(h));
    g_Whi[(size_t)n * DDIM + k0 + tx] = h;
    g_Wlo[(size_t)n * DDIM + k0 + tx] = l;
  }
}

// ---------------- k-select ----------------
__global__ void k_select_kernel(const float* __restrict__ k_logits,
                                float* __restrict__ out_ek,
                                uint32_t r1k0, uint32_t r1k1) {
  __shared__ float z[MAXK];
  int t = threadIdx.x;
  if (t < MAXK) z[t] = k_logits[t] + gumbel_at(r1k0, r1k1, (uint32_t)t);
  __syncthreads();
  if (t == 0) {
    float m = -INFINITY; int am = 0;
    for (int i = 0; i < MAXK; i++) if (z[i] > m) { m = z[i]; am = i; }
    float s = 0.0f, e[MAXK];
    for (int i = 0; i < MAXK; i++) { e[i] = expf(z[i] - m); s += e[i]; }
    float ek = 0.0f;
    for (int i = 0; i < MAXK; i++) ek += (e[i] / s) * (float)(i + 1);
    out_ek[0] = ek;
    g_ksel = am + 1;
  }
}

// ---------------- fused HMMA GEMM -> logits ----------------
__device__ __forceinline__ void issue_stage(uint32_t sbase, int buf, int row0,
                                            int nb, int k0, int tid) {
  const uint32_t stg = sbase + buf * STAGE_BYTES;
#pragma unroll
  for (int i = 0; i < 8; i++) {
    int c = tid + i * 256;
    int seg = c >> 9;          // 0:Ahi 1:Alo 2:Bhi 3:Blo (warp-uniform)
    int cc = c & 511;
    int row = cc >> 2, half = cc & 3;
    const __nv_bfloat16* g;
    int grow;
    if (seg == 0)      { g = g_Xhi; grow = row0 + row; }
    else if (seg == 1) { g = g_Xlo; grow = row0 + row; }
    else if (seg == 2) { g = g_Whi; grow = nb + row; }
    else               { g = g_Wlo; grow = nb + row; }
    const void* gp = (const void*)(g + (((size_t)grow) << 10) + k0 + half * 8);
    uint32_t sp = stg + seg * 10240 + row * 80 + half * 16;
    cp16(sp, gp);
  }
}

__global__ __launch_bounds__(256, 2)
void gemm_logits_kernel(const float* __restrict__ b1, const float* __restrict__ W2) {
  extern __shared__ char smem[];
  const uint32_t sb = smem_u32(smem);
  const int tid = threadIdx.x;
  const int lane = tid & 31;
  const int wid = tid >> 5;
  const int wm = wid >> 1;          // 0..3  (m)
  const int wn = wid & 1;           // 0..1  (n)
  const int row0 = blockIdx.x * BM;

  float* b1s = (float*)(smem + B1S_OFF);
  float* w2s = (float*)(smem + W2S_OFF);
  float* red = (float*)(smem + RED_OFF);

  // prefetch stage 0
  issue_stage(sb, 0, row0, 0, 0, tid);
  CP_COMMIT();

  // stage b1 / W2
#pragma unroll
  for (int i = 0; i < 8; i++) {
    b1s[tid + i * 256] = b1[tid + i * 256];
    w2s[tid + i * 256] = W2[tid + i * 256];
  }

  float C[2][8][4];
#pragma unroll
  for (int mi = 0; mi < 2; mi++)
#pragma unroll
    for (int ni = 0; ni < 8; ni++)
#pragma unroll
      for (int j = 0; j < 4; j++) C[mi][ni][j] = 0.0f;
  float lacc[4] = {0.0f, 0.0f, 0.0f, 0.0f};

  const int lr = lane & 15, lh = lane >> 4;

  for (int s = 0; s < NSTAGES; s++) {
    const int buf = s & 1;
    // retire the group for this stage's buffer, then one barrier that both
    // publishes buf s and certifies buf (s+1)&1 readers are done (prev iter).
    CP_WAIT0();
    __syncthreads();
    if (s + 1 < NSTAGES) {
      int s1 = s + 1;
      issue_stage(sb, s1 & 1, row0, (s1 >> 5) * BN, (s1 & 31) * BK, tid);
      CP_COMMIT();
    }

    const uint32_t stg = sb + buf * STAGE_BYTES;
    const uint32_t aB = stg + (wm * 32 + lr) * 80 + lh * 16;
    const uint32_t bB = stg + 20480 + (wn * 64 + lr) * 80 + lh * 16;
#pragma unroll
    for (int k16 = 0; k16 < 2; k16++) {
      uint32_t ah[2][4], al[2][4], b[8][2];
      ldsm4(ah[0], aB + k16 * 32);
      ldsm4(ah[1], aB + 16 * 80 + k16 * 32);
      ldsm4(al[0], aB + 10240 + k16 * 32);
      ldsm4(al[1], aB + 10240 + 16 * 80 + k16 * 32);
      // Bhi pass (hi*Bhi + lo*Bhi)
#pragma unroll
      for (int nt2 = 0; nt2 < 4; nt2++) {
        uint32_t r[4];
        ldsm4(r, bB + nt2 * (16 * 80) + k16 * 32);
        b[2 * nt2][0] = r[0]; b[2 * nt2][1] = r[2];
        b[2 * nt2 + 1][0] = r[1]; b[2 * nt2 + 1][1] = r[3];
      }
#pragma unroll
      for (int mi = 0; mi < 2; mi++)
#pragma unroll
        for (int ni = 0; ni < 8; ni++) mma16816(C[mi][ni], ah[mi], b[ni]);
#pragma unroll
      for (int mi = 0; mi < 2; mi++)
#pragma unroll
        for (int ni = 0; ni < 8; ni++) mma16816(C[mi][ni], al[mi], b[ni]);
      // Blo pass (hi*Blo), reuse b regs
#pragma unroll
      for (int nt2 = 0; nt2 < 4; nt2++) {
        uint32_t r[4];
        ldsm4(r, bB + 10240 + nt2 * (16 * 80) + k16 * 32);
        b[2 * nt2][0] = r[0]; b[2 * nt2][1] = r[2];
        b[2 * nt2 + 1][0] = r[1]; b[2 * nt2 + 1][1] = r[3];
      }
#pragma unroll
      for (int mi = 0; mi < 2; mi++)
#pragma unroll
        for (int ni = 0; ni < 8; ni++) mma16816(C[mi][ni], ah[mi], b[ni]);
    }

    if ((s & 31) == 31) {
      // epilogue for n-chunk nc = s >> 5 (registers + read-only smem; no barrier)
      const int colbase = (s >> 5) * BN + wn * 64 + (lane & 3) * 2;
#pragma unroll
      for (int ni = 0; ni < 8; ni++) {
        const int c0 = colbase + ni * 8;
        const float b10 = b1s[c0], b11 = b1s[c0 + 1];
        const float w20 = w2s[c0], w21 = w2s[c0 + 1];
#pragma unroll
        for (int mi = 0; mi < 2; mi++) {
          lacc[mi * 2 + 0] += fmaxf(C[mi][ni][0] + b10, 0.0f) * w20
                            + fmaxf(C[mi][ni][1] + b11, 0.0f) * w21;
          lacc[mi * 2 + 1] += fmaxf(C[mi][ni][2] + b10, 0.0f) * w20
                            + fmaxf(C[mi][ni][3] + b11, 0.0f) * w21;
          C[mi][ni][0] = 0.0f; C[mi][ni][1] = 0.0f;
          C[mi][ni][2] = 0.0f; C[mi][ni][3] = 0.0f;
        }
      }
    }
  }

  // reduce lacc over the quad (columns) -> row partials per n-warp
#pragma unroll
  for (int j = 0; j < 4; j++) {
    lacc[j] += __shfl_xor_sync(0xFFFFFFFFu, lacc[j], 1);
    lacc[j] += __shfl_xor_sync(0xFFFFFFFFu, lacc[j], 2);
  }
  __syncthreads();
  if ((lane & 3) == 0) {
    const int r = lane >> 2;
    red[wn * 128 + wm * 32 + r]      = lacc[0];
    red[wn * 128 + wm * 32 + 8 + r]  = lacc[1];
    red[wn * 128 + wm * 32 + 16 + r] = lacc[2];
    red[wn * 128 + wm * 32 + 24 + r] = lacc[3];
  }
  __syncthreads();
  if (tid < BM) g_logits[row0 + tid] = red[tid] + red[128 + tid];
}

// ---------------- top-k ----------------
__global__ __launch_bounds__(1024)
void topk_kernel(const float* __restrict__ b2, float* __restrict__ out_mask,
                 uint32_t r2k0, uint32_t r2k1) {
  __shared__ float vals[SEQ];
  __shared__ float msk[SEQ];
  __shared__ float wv[32];
  __shared__ int wi[32];
  const int row = blockIdx.x;
  const int tid = threadIdx.x;
  const int w = tid >> 5, l = tid & 31;
  const float bias2 = b2[0];

#pragma unroll
  for (int j = 0; j < 4; j++) {
    int i = tid + j * 1024;
    uint32_t idx = (uint32_t)(row * SEQ + i);
    vals[i] = g_logits[idx] + bias2 + gumbel_at(r2k0, r2k1, idx);
    msk[i] = 0.0f;
  }
  __syncthreads();

  const int k = g_ksel;
  for (int it = 0; it < k; it++) {
    float best = -INFINITY; int bi = SEQ;
#pragma unroll
    for (int j = 0; j < 4; j++) {
      int i = tid + j * 1024;
      float v = vals[i];
      if (v > best || (v == best && i < bi)) { best = v; bi = i; }
    }
#pragma unroll
    for (int off = 16; off > 0; off >>= 1) {
      float ov = __shfl_down_sync(0xFFFFFFFFu, best, off);
      int oi = __shfl_down_sync(0xFFFFFFFFu, bi, off);
      if (ov > best || (ov == best && oi < bi)) { best = ov; bi = oi; }
    }
    if (l == 0) { wv[w] = best; wi[w] = bi; }
    __syncthreads();
    if (tid < 32) {
      best = wv[tid]; bi = wi[tid];
#pragma unroll
      for (int off = 16; off > 0; off >>= 1) {
        float ov = __shfl_down_sync(0xFFFFFFFFu, best, off);
        int oi = __shfl_down_sync(0xFFFFFFFFu, bi, off);
        if (ov > best || (ov == best && oi < bi)) { best = ov; bi = oi; }
      }
      if (tid == 0) { vals[bi] = -INFINITY; msk[bi] = 1.0f; }
    }
    __syncthreads();
  }
#pragma unroll
  for (int j = 0; j < 4; j++) {
    int i = tid + j * 1024;
    float m = msk[i];
    out_mask[row * SEQ + i] = m;
    g_mask[row * SEQ + i] = m;
  }
}

// ---------------- scatter ----------------
__global__ __launch_bounds__(256)
void scatter_kernel(const float* __restrict__ X, float* __restrict__ out) {
  const int t = blockIdx.x;
  const int tid = threadIdx.x;
  const float m = g_mask[t];
  float4* dst = (float4*)(out + (size_t)t * DDIM);
  if (m != 0.0f) {
    const float4* src = (const float4*)(X + (size_t)t * DDIM);
    dst[tid] = src[tid];
  } else {
    dst[tid] = make_float4(0.0f, 0.0f, 0.0f, 0.0f);
  }
}

// ---------------- launch ----------------
extern "C" void kernel_launch(void* const* d_in, const int* in_sizes, int n_in,
                              void* d_out, int out_size) {
  const float* X  = (const float*)d_in[0];
  const float* W1 = (const float*)d_in[1];
  const float* b1 = (const float*)d_in[2];
  const float* W2 = (const float*)d_in[3];
  const float* b2 = (const float*)d_in[4];
  const float* kl = (const float*)d_in[5];

  float* out = (float*)d_out;
  float* out_mask = out + (size_t)NTOK * DDIM;
  float* out_ek   = out_mask + NTOK;

  uint32_t r1k0, r1k1, r2k0, r2k1;
  tf2x32(0u, 42u, 0u, 0u, &r1k0, &r1k1);
  tf2x32(0u, 42u, 0u, 1u, &r2k0, &r2k1);

  cudaFuncSetAttribute(gemm_logits_kernel,
                       cudaFuncAttributeMaxDynamicSharedMemorySize, DYN_SMEM);

  convX_kernel<<<(NTOK * DDIM / 4) / 256, 256>>>(X);
  convW_kernel<<<dim3(HDIM / 32, DDIM / 32), 256>>>(W1);
  k_select_kernel<<<1, 64>>>(kl, out_ek, r1k0, r1k1);
  gemm_logits_kernel<<<NTOK / BM, 256, DYN_SMEM>>>(b1, W2);
  topk_kernel<<<BATCH, 1024>>>(b2, out_mask, r2k0, r2k1);
  scatter_kernel<<<NTOK, 256>>>(X, out);
}

// round 5
// speedup vs baseline: 2.6924x; 1.0081x over previous
#include <cuda_runtime.h>
#include <cuda_bf16.h>
#include <stdint.h>
#include <math.h>

#define NTOK 32768
#define BATCH 8
#define SEQ 4096
#define DDIM 1024
#define HDIM 2048
#define MAXK 64

#define BM 128
#define BN 256
#define BK 32
#define NCHUNKS (HDIM / BN)          // 8
#define KSTAGES (DDIM / BK)          // 32
#define NSTAGES (NCHUNKS * KSTAGES)  // 256

// smem: 3 stages of [Ahi 10240][Alo 10240][Bhi 20480][Blo 20480] = 61440 each
#define STAGE_BYTES 61440
#define B1S_OFF  (3 * STAGE_BYTES)          // 184320
#define W2S_OFF  (B1S_OFF + 8192)           // 192512
#define RED_OFF  (W2S_OFF + 8192)           // 200704
#define DYN_SMEM (RED_OFF + 2048)           // 202752

// ---------------- scratch ----------------
static __device__ float g_logits[NTOK];
static __device__ float g_mask[NTOK];
static __device__ int   g_ksel;
static __device__ __nv_bfloat16 g_Xhi[(size_t)NTOK * DDIM];
static __device__ __nv_bfloat16 g_Xlo[(size_t)NTOK * DDIM];
static __device__ __nv_bfloat16 g_Whi[(size_t)HDIM * DDIM];  // n-major (transposed)
static __device__ __nv_bfloat16 g_Wlo[(size_t)HDIM * DDIM];

// ---------------- PTX helpers ----------------
__device__ __forceinline__ uint32_t smem_u32(const void* p) {
  uint32_t a;
  asm("{ .reg .u64 t; cvta.to.shared.u64 t, %1; cvt.u32.u64 %0, t; }" : "=r"(a) : "l"(p));
  return a;
}
__device__ __forceinline__ void cp16(uint32_t saddr, const void* gaddr) {
  asm volatile("cp.async.cg.shared.global [%0], [%1], 16;" :: "r"(saddr), "l"(gaddr));
}
#define CP_COMMIT() asm volatile("cp.async.commit_group;" ::: "memory")
#define CP_WAIT1()  asm volatile("cp.async.wait_group 1;" ::: "memory")
#define CP_WAIT0()  asm volatile("cp.async.wait_group 0;" ::: "memory")

__device__ __forceinline__ void ldsm4(uint32_t* r, uint32_t addr) {
  asm volatile("ldmatrix.sync.aligned.m8n8.x4.shared.b16 {%0,%1,%2,%3}, [%4];"
               : "=r"(r[0]), "=r"(r[1]), "=r"(r[2]), "=r"(r[3]) : "r"(addr));
}
__device__ __forceinline__ void mma16816(float* c, const uint32_t* a, const uint32_t* b) {
  asm volatile("mma.sync.aligned.m16n8k16.row.col.f32.bf16.bf16.f32 "
               "{%0,%1,%2,%3}, {%4,%5,%6,%7}, {%8,%9}, {%0,%1,%2,%3};"
               : "+f"(c[0]), "+f"(c[1]), "+f"(c[2]), "+f"(c[3])
               : "r"(a[0]), "r"(a[1]), "r"(a[2]), "r"(a[3]), "r"(b[0]), "r"(b[1]));
}

// ---------------- threefry2x32-20 (JAX) ----------------
__host__ __device__ __forceinline__ void tf2x32(uint32_t k0, uint32_t k1,
                                                uint32_t x0, uint32_t x1,
                                                uint32_t* o0, uint32_t* o1) {
  uint32_t ks2 = k0 ^ k1 ^ 0x1BD11BDAu;
#define ROTL(v, d) (((v) << (d)) | ((v) >> (32 - (d))))
#define RND(r) { x0 += x1; x1 = ROTL(x1, r); x1 ^= x0; }
  x0 += k0; x1 += k1;
  RND(13) RND(15) RND(26) RND(6)
  x0 += k1; x1 += ks2 + 1u;
  RND(17) RND(29) RND(16) RND(24)
  x0 += ks2; x1 += k0 + 2u;
  RND(13) RND(15) RND(26) RND(6)
  x0 += k0; x1 += k1 + 3u;
  RND(17) RND(29) RND(16) RND(24)
  x0 += k1; x1 += ks2 + 4u;
  RND(13) RND(15) RND(26) RND(6)
  x0 += ks2; x1 += k0 + 5u;
#undef RND
#undef ROTL
  *o0 = x0; *o1 = x1;
}
__device__ __forceinline__ float gumbel_at(uint32_t k0, uint32_t k1, uint32_t idx) {
  uint32_t a, b;
  tf2x32(k0, k1, 0u, idx, &a, &b);
  uint32_t bits = a ^ b;
  float u = __uint_as_float((bits >> 9) | 0x3f800000u) - 1.0f;
  u = u + 1e-8f;
  u = fmaxf(1e-8f, u);
  return -logf(-logf(u));
}

// ---------------- conversion kernels ----------------
__global__ __launch_bounds__(256) void convX_kernel(const float* __restrict__ X) {
  size_t i = (size_t)blockIdx.x * 256 + threadIdx.x;   // float4 index
  float4 v = ((const float4*)X)[i];
  __nv_bfloat16 h0 = __float2bfloat16(v.x), h1 = __float2bfloat16(v.y);
  __nv_bfloat16 h2 = __float2bfloat16(v.z), h3 = __float2bfloat16(v.w);
  __nv_bfloat16 l0 = __float2bfloat16(v.x - __bfloat162float(h0));
  __nv_bfloat16 l1 = __float2bfloat16(v.y - __bfloat162float(h1));
  __nv_bfloat16 l2 = __float2bfloat16(v.z - __bfloat162float(h2));
  __nv_bfloat16 l3 = __float2bfloat16(v.w - __bfloat162float(h3));
  __nv_bfloat162* H = (__nv_bfloat162*)g_Xhi;
  __nv_bfloat162* L = (__nv_bfloat162*)g_Xlo;
  H[i * 2] = __nv_bfloat162(h0, h1); H[i * 2 + 1] = __nv_bfloat162(h2, h3);
  L[i * 2] = __nv_bfloat162(l0, l1); L[i * 2 + 1] = __nv_bfloat162(l2, l3);
}

__global__ __launch_bounds__(256) void convW_kernel(const float* __restrict__ W1) {
  __shared__ float s[32][33];
  int n0 = blockIdx.x * 32;
  int k0 = blockIdx.y * 32;
  int tx = threadIdx.x & 31, ty = threadIdx.x >> 5;   // ty 0..7
#pragma unroll
  for (int j = 0; j < 4; j++) {
    int k = k0 + ty + j * 8;
    s[ty + j * 8][tx] = W1[(size_t)k * HDIM + n0 + tx];
  }
  __syncthreads();
#pragma unroll
  for (int j = 0; j < 4; j++) {
    int n = n0 + ty + j * 8;
    float v = s[tx][ty + j * 8];
    __nv_bfloat16 h = __float2bfloat16(v);
    __nv_bfloat16 l = __float2bfloat16(v - __bfloat162float(h));
    g_Whi[(size_t)n * DDIM + k0 + tx] = h;
    g_Wlo[(size_t)n * DDIM + k0 + tx] = l;
  }
}

// ---------------- k-select ----------------
__global__ void k_select_kernel(const float* __restrict__ k_logits,
                                float* __restrict__ out_ek,
                                uint32_t r1k0, uint32_t r1k1) {
  __shared__ float z[MAXK];
  int t = threadIdx.x;
  if (t < MAXK) z[t] = k_logits[t] + gumbel_at(r1k0, r1k1, (uint32_t)t);
  __syncthreads();
  if (t == 0) {
    float m = -INFINITY; int am = 0;
    for (int i = 0; i < MAXK; i++) if (z[i] > m) { m = z[i]; am = i; }
    float s = 0.0f, e[MAXK];
    for (int i = 0; i < MAXK; i++) { e[i] = expf(z[i] - m); s += e[i]; }
    float ek = 0.0f;
    for (int i = 0; i < MAXK; i++) ek += (e[i] / s) * (float)(i + 1);
    out_ek[0] = ek;
    g_ksel = am + 1;
  }
}

// ---------------- fused HMMA GEMM -> logits ----------------
// 3072 16B data-chunks per stage: [Ahi 512][Alo 512][Bhi 1024][Blo 1024]
// 512 threads x 6 chunks, segment uniform per step.
__device__ __forceinline__ void issue_stage(uint32_t stg, int row0, int nb,
                                            int k0, int tid) {
  {  // i=0: Ahi   (chunk c = tid, 0..511)
    int row = tid >> 2, half = tid & 3;
    cp16(stg + row * 80 + half * 16,
         (const void*)(g_Xhi + (((size_t)(row0 + row)) << 10) + k0 + half * 8));
  }
  {  // i=1: Alo
    int row = tid >> 2, half = tid & 3;
    cp16(stg + 10240 + row * 80 + half * 16,
         (const void*)(g_Xlo + (((size_t)(row0 + row)) << 10) + k0 + half * 8));
  }
#pragma unroll
  for (int j = 0; j < 2; j++) {  // i=2,3: Bhi (cc = tid + j*512, 0..1023)
    int cc = tid + j * 512;
    int row = cc >> 2, half = cc & 3;
    cp16(stg + 20480 + row * 80 + half * 16,
         (const void*)(g_Whi + (((size_t)(nb + row)) << 10) + k0 + half * 8));
  }
#pragma unroll
  for (int j = 0; j < 2; j++) {  // i=4,5: Blo
    int cc = tid + j * 512;
    int row = cc >> 2, half = cc & 3;
    cp16(stg + 40960 + row * 80 + half * 16,
         (const void*)(g_Wlo + (((size_t)(nb + row)) << 10) + k0 + half * 8));
  }
}

__global__ __launch_bounds__(512, 1)
void gemm_logits_kernel(const float* __restrict__ b1, const float* __restrict__ W2) {
  extern __shared__ char smem[];
  const uint32_t sb = smem_u32(smem);
  const int tid = threadIdx.x;
  const int lane = tid & 31;
  const int wid = tid >> 5;
  const int wm = wid & 3;           // 0..3 (m, 32-row slices)
  const int wn = wid >> 2;          // 0..3 (n, 64-col slices)
  const int row0 = blockIdx.x * BM;

  float* b1s = (float*)(smem + B1S_OFF);
  float* w2s = (float*)(smem + W2S_OFF);
  float* red = (float*)(smem + RED_OFF);

  // prefetch stages 0 and 1
  issue_stage(sb, row0, 0, 0, tid);
  CP_COMMIT();
  issue_stage(sb + STAGE_BYTES, row0, 0, BK, tid);
  CP_COMMIT();

  // stage b1 / W2 (consumed first at stage 31, published by loop barriers)
#pragma unroll
  for (int i = 0; i < 4; i++) {
    b1s[tid + i * 512] = b1[tid + i * 512];
    w2s[tid + i * 512] = W2[tid + i * 512];
  }

  float C[2][8][4];
#pragma unroll
  for (int mi = 0; mi < 2; mi++)
#pragma unroll
    for (int ni = 0; ni < 8; ni++)
#pragma unroll
      for (int j = 0; j < 4; j++) C[mi][ni][j] = 0.0f;
  float lacc[4] = {0.0f, 0.0f, 0.0f, 0.0f};

  const int lr = lane & 15, lh = lane >> 4;

  int buf = 0;       // buffer of stage s (s mod 3)
  for (int s = 0; s < NSTAGES; s++) {
    // stage s guaranteed in, stage s+1 may still be in flight
    if (s + 2 < NSTAGES) CP_WAIT1(); else CP_WAIT0();
    __syncthreads();   // publish buf s; certify compute(s-1) done -> buf(s-1) reusable
    if (s + 2 < NSTAGES) {
      int s2 = s + 2;
      int b2i = buf + 2; if (b2i >= 3) b2i -= 3;
      issue_stage(sb + b2i * STAGE_BYTES, row0, (s2 >> 5) * BN, (s2 & 31) * BK, tid);
      CP_COMMIT();
    }

    const uint32_t stg = sb + buf * STAGE_BYTES;
    const uint32_t aB = stg + (wm * 32 + lr) * 80 + lh * 16;
    const uint32_t bB = stg + 20480 + (wn * 64 + lr) * 80 + lh * 16;
#pragma unroll
    for (int k16 = 0; k16 < 2; k16++) {
      uint32_t ah[2][4], al[2][4], b[8][2];
      ldsm4(ah[0], aB + k16 * 32);
      ldsm4(ah[1], aB + 16 * 80 + k16 * 32);
      ldsm4(al[0], aB + 10240 + k16 * 32);
      ldsm4(al[1], aB + 10240 + 16 * 80 + k16 * 32);
      // Bhi pass (hi*Bhi + lo*Bhi)
#pragma unroll
      for (int nt2 = 0; nt2 < 4; nt2++) {
        uint32_t r[4];
        ldsm4(r, bB + nt2 * (16 * 80) + k16 * 32);
        b[2 * nt2][0] = r[0]; b[2 * nt2][1] = r[2];
        b[2 * nt2 + 1][0] = r[1]; b[2 * nt2 + 1][1] = r[3];
      }
#pragma unroll
      for (int mi = 0; mi < 2; mi++)
#pragma unroll
        for (int ni = 0; ni < 8; ni++) mma16816(C[mi][ni], ah[mi], b[ni]);
#pragma unroll
      for (int mi = 0; mi < 2; mi++)
#pragma unroll
        for (int ni = 0; ni < 8; ni++) mma16816(C[mi][ni], al[mi], b[ni]);
      // Blo pass (hi*Blo), reuse b regs
#pragma unroll
      for (int nt2 = 0; nt2 < 4; nt2++) {
        uint32_t r[4];
        ldsm4(r, bB + 20480 + nt2 * (16 * 80) + k16 * 32);
        b[2 * nt2][0] = r[0]; b[2 * nt2][1] = r[2];
        b[2 * nt2 + 1][0] = r[1]; b[2 * nt2 + 1][1] = r[3];
      }
#pragma unroll
      for (int mi = 0; mi < 2; mi++)
#pragma unroll
        for (int ni = 0; ni < 8; ni++) mma16816(C[mi][ni], ah[mi], b[ni]);
    }

    if ((s & 31) == 31) {
      // epilogue for n-chunk nc = s >> 5 (registers + read-only smem)
      const int colbase = (s >> 5) * BN + wn * 64 + (lane & 3) * 2;
#pragma unroll
      for (int ni = 0; ni < 8; ni++) {
        const int c0 = colbase + ni * 8;
        const float b10 = b1s[c0], b11 = b1s[c0 + 1];
        const float w20 = w2s[c0], w21 = w2s[c0 + 1];
#pragma unroll
        for (int mi = 0; mi < 2; mi++) {
          lacc[mi * 2 + 0] += fmaxf(C[mi][ni][0] + b10, 0.0f) * w20
                            + fmaxf(C[mi][ni][1] + b11, 0.0f) * w21;
          lacc[mi * 2 + 1] += fmaxf(C[mi][ni][2] + b10, 0.0f) * w20
                            + fmaxf(C[mi][ni][3] + b11, 0.0f) * w21;
          C[mi][ni][0] = 0.0f; C[mi][ni][1] = 0.0f;
          C[mi][ni][2] = 0.0f; C[mi][ni][3] = 0.0f;
        }
      }
    }
    buf++; if (buf == 3) buf = 0;
  }

  // reduce lacc over the quad (columns) -> row partials per n-warp
#pragma unroll
  for (int j = 0; j < 4; j++) {
    lacc[j] += __shfl_xor_sync(0xFFFFFFFFu, lacc[j], 1);
    lacc[j] += __shfl_xor_sync(0xFFFFFFFFu, lacc[j], 2);
  }
  __syncthreads();
  if ((lane & 3) == 0) {
    const int r = lane >> 2;
    red[wn * 128 + wm * 32 + r]      = lacc[0];
    red[wn * 128 + wm * 32 + 8 + r]  = lacc[1];
    red[wn * 128 + wm * 32 + 16 + r] = lacc[2];
    red[wn * 128 + wm * 32 + 24 + r] = lacc[3];
  }
  __syncthreads();
  if (tid < BM)
    g_logits[row0 + tid] = (red[tid] + red[128 + tid]) + (red[256 + tid] + red[384 + tid]);
}

// ---------------- top-k ----------------
__global__ __launch_bounds__(1024)
void topk_kernel(const float* __restrict__ b2, float* __restrict__ out_mask,
                 uint32_t r2k0, uint32_t r2k1) {
  __shared__ float vals[SEQ];
  __shared__ float msk[SEQ];
  __shared__ float wv[32];
  __shared__ int wi[32];
  const int row = blockIdx.x;
  const int tid = threadIdx.x;
  const int w = tid >> 5, l = tid & 31;
  const float bias2 = b2[0];

#pragma unroll
  for (int j = 0; j < 4; j++) {
    int i = tid + j * 1024;
    uint32_t idx = (uint32_t)(row * SEQ + i);
    vals[i] = g_logits[idx] + bias2 + gumbel_at(r2k0, r2k1, idx);
    msk[i] = 0.0f;
  }
  __syncthreads();

  const int k = g_ksel;
  for (int it = 0; it < k; it++) {
    float best = -INFINITY; int bi = SEQ;
#pragma unroll
    for (int j = 0; j < 4; j++) {
      int i = tid + j * 1024;
      float v = vals[i];
      if (v > best || (v == best && i < bi)) { best = v; bi = i; }
    }
#pragma unroll
    for (int off = 16; off > 0; off >>= 1) {
      float ov = __shfl_down_sync(0xFFFFFFFFu, best, off);
      int oi = __shfl_down_sync(0xFFFFFFFFu, bi, off);
      if (ov > best || (ov == best && oi < bi)) { best = ov; bi = oi; }
    }
    if (l == 0) { wv[w] = best; wi[w] = bi; }
    __syncthreads();
    if (tid < 32) {
      best = wv[tid]; bi = wi[tid];
#pragma unroll
      for (int off = 16; off > 0; off >>= 1) {
        float ov = __shfl_down_sync(0xFFFFFFFFu, best, off);
        int oi = __shfl_down_sync(0xFFFFFFFFu, bi, off);
        if (ov > best || (ov == best && oi < bi)) { best = ov; bi = oi; }
      }
      if (tid == 0) { vals[bi] = -INFINITY; msk[bi] = 1.0f; }
    }
    __syncthreads();
  }
#pragma unroll
  for (int j = 0; j < 4; j++) {
    int i = tid + j * 1024;
    float m = msk[i];
    out_mask[row * SEQ + i] = m;
    g_mask[row * SEQ + i] = m;
  }
}

// ---------------- scatter ----------------
__global__ __launch_bounds__(256)
void scatter_kernel(const float* __restrict__ X, float* __restrict__ out) {
  const int t = blockIdx.x;
  const int tid = threadIdx.x;
  const float m = g_mask[t];
  float4* dst = (float4*)(out + (size_t)t * DDIM);
  if (m != 0.0f) {
    const float4* src = (const float4*)(X + (size_t)t * DDIM);
    dst[tid] = src[tid];
  } else {
    dst[tid] = make_float4(0.0f, 0.0f, 0.0f, 0.0f);
  }
}

// ---------------- launch ----------------
extern "C" void kernel_launch(void* const* d_in, const int* in_sizes, int n_in,
                              void* d_out, int out_size) {
  const float* X  = (const float*)d_in[0];
  const float* W1 = (const float*)d_in[1];
  const float* b1 = (const float*)d_in[2];
  const float* W2 = (const float*)d_in[3];
  const float* b2 = (const float*)d_in[4];
  const float* kl = (const float*)d_in[5];

  float* out = (float*)d_out;
  float* out_mask = out + (size_t)NTOK * DDIM;
  float* out_ek   = out_mask + NTOK;

  uint32_t r1k0, r1k1, r2k0, r2k1;
  tf2x32(0u, 42u, 0u, 0u, &r1k0, &r1k1);
  tf2x32(0u, 42u, 0u, 1u, &r2k0, &r2k1);

  cudaFuncSetAttribute(gemm_logits_kernel,
                       cudaFuncAttributeMaxDynamicSharedMemorySize, DYN_SMEM);

  convX_kernel<<<(NTOK * DDIM / 4) / 256, 256>>>(X);
  convW_kernel<<<dim3(HDIM / 32, DDIM / 32), 256>>>(W1);
  k_select_kernel<<<1, 64>>>(kl, out_ek, r1k0, r1k1);
  gemm_logits_kernel<<<NTOK / BM, 512, DYN_SMEM>>>(b1, W2);
  topk_kernel<<<BATCH, 1024>>>(b2, out_mask, r2k0, r2k1);
  scatter_kernel<<<NTOK, 256>>>(X, out);
}

// round 7
// speedup vs baseline: 2.7861x; 1.0348x over previous
#include <cuda_runtime.h>
#include <cuda_bf16.h>
#include <stdint.h>
#include <math.h>

#define NTOK 32768
#define BATCH 8
#define SEQ 4096
#define DDIM 1024
#define HDIM 2048
#define MAXK 64

#define BM 128
#define BN 256
#define BK 32
#define NCHUNKS (HDIM / BN)          // 8
#define KSTAGES (DDIM / BK)          // 32
#define NSTAGES (NCHUNKS * KSTAGES)  // 256

// smem: 3 stages of [Ahi 10240][Alo 10240][Bhi 20480][Blo 20480] = 61440 each
#define STAGE_BYTES 61440
#define B1S_OFF  (3 * STAGE_BYTES)          // 184320
#define W2S_OFF  (B1S_OFF + 8192)           // 192512
#define RED_OFF  (W2S_OFF + 8192)           // 200704
#define DYN_SMEM (RED_OFF + 2048)           // 202752

// ---------------- scratch ----------------
static __device__ float g_logits[NTOK];
static __device__ float g_mask[NTOK];
static __device__ int   g_ksel;
static __device__ __nv_bfloat16 g_Xhi[(size_t)NTOK * DDIM];
static __device__ __nv_bfloat16 g_Xlo[(size_t)NTOK * DDIM];
static __device__ __nv_bfloat16 g_Whi[(size_t)HDIM * DDIM];  // n-major (transposed)
static __device__ __nv_bfloat16 g_Wlo[(size_t)HDIM * DDIM];

// ---------------- PTX helpers ----------------
__device__ __forceinline__ uint32_t smem_u32(const void* p) {
  uint32_t a;
  asm("{ .reg .u64 t; cvta.to.shared.u64 t, %1; cvt.u32.u64 %0, t; }" : "=r"(a) : "l"(p));
  return a;
}
__device__ __forceinline__ void cp16(uint32_t saddr, const void* gaddr) {
  asm volatile("cp.async.cg.shared.global [%0], [%1], 16;" :: "r"(saddr), "l"(gaddr));
}
#define CP_COMMIT() asm volatile("cp.async.commit_group;" ::: "memory")
#define CP_WAIT1()  asm volatile("cp.async.wait_group 1;" ::: "memory")
#define CP_WAIT0()  asm volatile("cp.async.wait_group 0;" ::: "memory")

__device__ __forceinline__ void ldsm4(uint32_t* r, uint32_t addr) {
  asm volatile("ldmatrix.sync.aligned.m8n8.x4.shared.b16 {%0,%1,%2,%3}, [%4];"
               : "=r"(r[0]), "=r"(r[1]), "=r"(r[2]), "=r"(r[3]) : "r"(addr));
}
// load one n16xk16 B tile -> two n8 fragments b[0..1][0..1]
__device__ __forceinline__ void ldsm_b2(uint32_t (*b)[2], uint32_t addr) {
  uint32_t r[4];
  ldsm4(r, addr);
  b[0][0] = r[0]; b[0][1] = r[2];
  b[1][0] = r[1]; b[1][1] = r[3];
}
__device__ __forceinline__ void mma16816(float* c, const uint32_t* a, const uint32_t* b) {
  asm volatile("mma.sync.aligned.m16n8k16.row.col.f32.bf16.bf16.f32 "
               "{%0,%1,%2,%3}, {%4,%5,%6,%7}, {%8,%9}, {%0,%1,%2,%3};"
               : "+f"(c[0]), "+f"(c[1]), "+f"(c[2]), "+f"(c[3])
               : "r"(a[0]), "r"(a[1]), "r"(a[2]), "r"(a[3]), "r"(b[0]), "r"(b[1]));
}

// ---------------- threefry2x32-20 (JAX) ----------------
__host__ __device__ __forceinline__ void tf2x32(uint32_t k0, uint32_t k1,
                                                uint32_t x0, uint32_t x1,
                                                uint32_t* o0, uint32_t* o1) {
  uint32_t ks2 = k0 ^ k1 ^ 0x1BD11BDAu;
#define ROTL(v, d) (((v) << (d)) | ((v) >> (32 - (d))))
#define RND(r) { x0 += x1; x1 = ROTL(x1, r); x1 ^= x0; }
  x0 += k0; x1 += k1;
  RND(13) RND(15) RND(26) RND(6)
  x0 += k1; x1 += ks2 + 1u;
  RND(17) RND(29) RND(16) RND(24)
  x0 += ks2; x1 += k0 + 2u;
  RND(13) RND(15) RND(26) RND(6)
  x0 += k0; x1 += k1 + 3u;
  RND(17) RND(29) RND(16) RND(24)
  x0 += k1; x1 += ks2 + 4u;
  RND(13) RND(15) RND(26) RND(6)
  x0 += ks2; x1 += k0 + 5u;
#undef RND
#undef ROTL
  *o0 = x0; *o1 = x1;
}
__device__ __forceinline__ float gumbel_at(uint32_t k0, uint32_t k1, uint32_t idx) {
  uint32_t a, b;
  tf2x32(k0, k1, 0u, idx, &a, &b);
  uint32_t bits = a ^ b;
  float u = __uint_as_float((bits >> 9) | 0x3f800000u) - 1.0f;
  u = u + 1e-8f;
  u = fmaxf(1e-8f, u);
  return -logf(-logf(u));
}

// ---------------- conversion kernels ----------------
__global__ __launch_bounds__(256) void convX_kernel(const float* __restrict__ X) {
  size_t i = (size_t)blockIdx.x * 256 + threadIdx.x;   // float4 index
  float4 v = ((const float4*)X)[i];
  __nv_bfloat16 h0 = __float2bfloat16(v.x), h1 = __float2bfloat16(v.y);
  __nv_bfloat16 h2 = __float2bfloat16(v.z), h3 = __float2bfloat16(v.w);
  __nv_bfloat16 l0 = __float2bfloat16(v.x - __bfloat162float(h0));
  __nv_bfloat16 l1 = __float2bfloat16(v.y - __bfloat162float(h1));
  __nv_bfloat16 l2 = __float2bfloat16(v.z - __bfloat162float(h2));
  __nv_bfloat16 l3 = __float2bfloat16(v.w - __bfloat162float(h3));
  __nv_bfloat162* H = (__nv_bfloat162*)g_Xhi;
  __nv_bfloat162* L = (__nv_bfloat162*)g_Xlo;
  H[i * 2] = __nv_bfloat162(h0, h1); H[i * 2 + 1] = __nv_bfloat162(h2, h3);
  L[i * 2] = __nv_bfloat162(l0, l1); L[i * 2 + 1] = __nv_bfloat162(l2, l3);
}

__global__ __launch_bounds__(256) void convW_kernel(const float* __restrict__ W1) {
  __shared__ float s[32][33];
  int n0 = blockIdx.x * 32;
  int k0 = blockIdx.y * 32;
  int tx = threadIdx.x & 31, ty = threadIdx.x >> 5;   // ty 0..7
#pragma unroll
  for (int j = 0; j < 4; j++) {
    int k = k0 + ty + j * 8;
    s[ty + j * 8][tx] = W1[(size_t)k * HDIM + n0 + tx];
  }
  __syncthreads();
#pragma unroll
  for (int j = 0; j < 4; j++) {
    int n = n0 + ty + j * 8;
    float v = s[tx][ty + j * 8];
    __nv_bfloat16 h = __float2bfloat16(v);
    __nv_bfloat16 l = __float2bfloat16(v - __bfloat162float(h));
    g_Whi[(size_t)n * DDIM + k0 + tx] = h;
    g_Wlo[(size_t)n * DDIM + k0 + tx] = l;
  }
}

// ---------------- k-select ----------------
__global__ void k_select_kernel(const float* __restrict__ k_logits,
                                float* __restrict__ out_ek,
                                uint32_t r1k0, uint32_t r1k1) {
  __shared__ float z[MAXK];
  int t = threadIdx.x;
  if (t < MAXK) z[t] = k_logits[t] + gumbel_at(r1k0, r1k1, (uint32_t)t);
  __syncthreads();
  if (t == 0) {
    float m = -INFINITY; int am = 0;
    for (int i = 0; i < MAXK; i++) if (z[i] > m) { m = z[i]; am = i; }
    float s = 0.0f, e[MAXK];
    for (int i = 0; i < MAXK; i++) { e[i] = expf(z[i] - m); s += e[i]; }
    float ek = 0.0f;
    for (int i = 0; i < MAXK; i++) ek += (e[i] / s) * (float)(i + 1);
    out_ek[0] = ek;
    g_ksel = am + 1;
  }
}

// ---------------- fused HMMA GEMM -> logits ----------------
__global__ __launch_bounds__(512, 1)
void gemm_logits_kernel(const float* __restrict__ b1, const float* __restrict__ W2) {
  extern __shared__ char smem[];
  const uint32_t sb = smem_u32(smem);
  const int tid = threadIdx.x;
  const int lane = tid & 31;
  const int wid = tid >> 5;
  const int wm = wid & 3;           // 0..3 (m, 32-row slices)
  const int wn = wid >> 2;          // 0..3 (n, 64-col slices)
  const int row0 = blockIdx.x * BM;

  float* b1s = (float*)(smem + B1S_OFF);
  float* w2s = (float*)(smem + W2S_OFF);
  float* red = (float*)(smem + RED_OFF);

  // ---- loader per-thread constants (incremental addressing) ----
  const int cr = tid >> 2, ch = tid & 3;              // chunk row / 16B-half
  const size_t rb = ((size_t)cr) << 11;               // row byte offset (2048B rows)
  const char* pXhiB = (const char*)g_Xhi + (((size_t)(row0 + cr)) << 11) + ch * 16;
  const char* pXloB = (const char*)g_Xlo + (((size_t)(row0 + cr)) << 11) + ch * 16;
  const char* pWhiB = (const char*)g_Whi + rb + ch * 16;
  const char* pWloB = (const char*)g_Wlo + rb + ch * 16;
  const uint32_t sA = (uint32_t)(cr * 80 + ch * 16);  // smem offset within segment

#define ISSUE_STAGE(stgbase, s2) do {                                        \
    const uint32_t _stg = (stgbase);                                         \
    const size_t _ko = (size_t)(((s2) & 31) << 6);                           \
    const size_t _nb = ((size_t)((s2) >> 5)) << 19;                          \
    cp16(_stg + sA,                 pXhiB + _ko);                            \
    cp16(_stg + 10240 + sA,         pXloB + _ko);                            \
    cp16(_stg + 20480 + sA,         pWhiB + _nb + _ko);                      \
    cp16(_stg + 30720 + sA,         pWhiB + _nb + (128ull << 11) + _ko);     \
    cp16(_stg + 40960 + sA,         pWloB + _nb + _ko);                      \
    cp16(_stg + 51200 + sA,         pWloB + _nb + (128ull << 11) + _ko);     \
  } while (0)

  // prefetch stages 0 and 1
  ISSUE_STAGE(sb, 0);
  CP_COMMIT();
  ISSUE_STAGE(sb + STAGE_BYTES, 1);
  CP_COMMIT();

  // stage b1 / W2 (published by the loop's per-stage barriers)
#pragma unroll
  for (int i = 0; i < 4; i++) {
    b1s[tid + i * 512] = b1[tid + i * 512];
    w2s[tid + i * 512] = W2[tid + i * 512];
  }

  float C[2][8][4];
#pragma unroll
  for (int mi = 0; mi < 2; mi++)
#pragma unroll
    for (int ni = 0; ni < 8; ni++)
#pragma unroll
      for (int j = 0; j < 4; j++) C[mi][ni][j] = 0.0f;
  float lacc[4] = {0.0f, 0.0f, 0.0f, 0.0f};

  const int lr = lane & 15, lh = lane >> 4;
  const uint32_t aOff = (uint32_t)((wm * 32 + lr) * 80 + lh * 16);
  const uint32_t bOff = (uint32_t)(20480 + (wn * 64 + lr) * 80 + lh * 16);

  int buf = 0;       // buffer of stage s (s mod 3)
  for (int s = 0; s < NSTAGES; s++) {
    // stage s guaranteed in, stage s+1 may still be in flight
    if (s + 2 < NSTAGES) CP_WAIT1(); else CP_WAIT0();
    __syncthreads();   // publish buf s; certify compute(s-1) done -> buf(s-1) reusable
    if (s + 2 < NSTAGES) {
      int b2i = buf + 2; if (b2i >= 3) b2i -= 3;
      ISSUE_STAGE(sb + b2i * STAGE_BYTES, s + 2);
      CP_COMMIT();
    }

    const uint32_t stg = sb + buf * STAGE_BYTES;
    const uint32_t aB = stg + aOff;
    const uint32_t bB = stg + bOff;
#pragma unroll
    for (int k16 = 0; k16 < 2; k16++) {
      uint32_t ah[2][4], al[2][4], bb0[4][2], bb1[4][2];
      const uint32_t kofs = k16 * 32;
      // A fragments
      ldsm4(ah[0], aB + kofs);
      ldsm4(ah[1], aB + 16 * 80 + kofs);
      ldsm4(al[0], aB + 10240 + kofs);
      ldsm4(al[1], aB + 10240 + 16 * 80 + kofs);
      // G0 (Bhi n[0,32)) + G1 (Bhi n[32,64)) loads
      ldsm_b2(bb0 + 0, bB + kofs);
      ldsm_b2(bb0 + 2, bB + 16 * 80 + kofs);
      ldsm_b2(bb1 + 0, bB + 2 * (16 * 80) + kofs);
      ldsm_b2(bb1 + 2, bB + 3 * (16 * 80) + kofs);
      // G0 compute (ah+al vs bb0 -> C[:,0..3])
#pragma unroll
      for (int mi = 0; mi < 2; mi++)
#pragma unroll
        for (int ni = 0; ni < 4; ni++) mma16816(C[mi][ni], ah[mi], bb0[ni]);
#pragma unroll
      for (int mi = 0; mi < 2; mi++)
#pragma unroll
        for (int ni = 0; ni < 4; ni++) mma16816(C[mi][ni], al[mi], bb0[ni]);
      // G2 load (Blo n[0,32)) into bb0 while G1 computes
      ldsm_b2(bb0 + 0, bB + 20480 + kofs);
      ldsm_b2(bb0 + 2, bB + 20480 + 16 * 80 + kofs);
      // G1 compute (ah+al vs bb1 -> C[:,4..7])
#pragma unroll
      for (int mi = 0; mi < 2; mi++)
#pragma unroll
        for (int ni = 0; ni < 4; ni++) mma16816(C[mi][ni + 4], ah[mi], bb1[ni]);
#pragma unroll
      for (int mi = 0; mi < 2; mi++)
#pragma unroll
        for (int ni = 0; ni < 4; ni++) mma16816(C[mi][ni + 4], al[mi], bb1[ni]);
      // G3 load (Blo n[32,64)) into bb1 while G2 computes
      ldsm_b2(bb1 + 0, bB + 20480 + 2 * (16 * 80) + kofs);
      ldsm_b2(bb1 + 2, bB + 20480 + 3 * (16 * 80) + kofs);
      // G2 compute (ah vs bb0 -> C[:,0..3])
#pragma unroll
      for (int mi = 0; mi < 2; mi++)
#pragma unroll
        for (int ni = 0; ni < 4; ni++) mma16816(C[mi][ni], ah[mi], bb0[ni]);
      // G3 compute (ah vs bb1 -> C[:,4..7])
#pragma unroll
      for (int mi = 0; mi < 2; mi++)
#pragma unroll
        for (int ni = 0; ni < 4; ni++) mma16816(C[mi][ni + 4], ah[mi], bb1[ni]);
    }

    if ((s & 31) == 31) {
      // epilogue for n-chunk nc = s >> 5 (registers + read-only smem)
      const int colbase = (s >> 5) * BN + wn * 64 + (lane & 3) * 2;
#pragma unroll
      for (int ni = 0; ni < 8; ni++) {
        const int c0 = colbase + ni * 8;
        const float b10 = b1s[c0], b11 = b1s[c0 + 1];
        const float w20 = w2s[c0], w21 = w2s[c0 + 1];
#pragma unroll
        for (int mi = 0; mi < 2; mi++) {
          lacc[mi * 2 + 0] += fmaxf(C[mi][ni][0] + b10, 0.0f) * w20
                            + fmaxf(C[mi][ni][1] + b11, 0.0f) * w21;
          lacc[mi * 2 + 1] += fmaxf(C[mi][ni][2] + b10, 0.0f) * w20
                            + fmaxf(C[mi][ni][3] + b11, 0.0f) * w21;
          C[mi][ni][0] = 0.0f; C[mi][ni][1] = 0.0f;
          C[mi][ni][2] = 0.0f; C[mi][ni][3] = 0.0f;
        }
      }
    }
    buf++; if (buf == 3) buf = 0;
  }

  // reduce lacc over the quad (columns) -> row partials per n-warp
#pragma unroll
  for (int j = 0; j < 4; j++) {
    lacc[j] += __shfl_xor_sync(0xFFFFFFFFu, lacc[j], 1);
    lacc[j] += __shfl_xor_sync(0xFFFFFFFFu, lacc[j], 2);
  }
  __syncthreads();
  if ((lane & 3) == 0) {
    const int r = lane >> 2;
    red[wn * 128 + wm * 32 + r]      = lacc[0];
    red[wn * 128 + wm * 32 + 8 + r]  = lacc[1];
    red[wn * 128 + wm * 32 + 16 + r] = lacc[2];
    red[wn * 128 + wm * 32 + 24 + r] = lacc[3];
  }
  __syncthreads();
  if (tid < BM)
    g_logits[row0 + tid] = (red[tid] + red[128 + tid]) + (red[256 + tid] + red[384 + tid]);
}

// ---------------- top-k ----------------
__global__ __launch_bounds__(1024)
void topk_kernel(const float* __restrict__ b2, float* __restrict__ out_mask,
                 uint32_t r2k0, uint32_t r2k1) {
  __shared__ float vals[SEQ];
  __shared__ float msk[SEQ];
  __shared__ float wv[32];
  __shared__ int wi[32];
  const int row = blockIdx.x;
  const int tid = threadIdx.x;
  const int w = tid >> 5, l = tid & 31;
  const float bias2 = b2[0];

#pragma unroll
  for (int j = 0; j < 4; j++) {
    int i = tid + j * 1024;
    uint32_t idx = (uint32_t)(row * SEQ + i);
    vals[i] = g_logits[idx] + bias2 + gumbel_at(r2k0, r2k1, idx);
    msk[i] = 0.0f;
  }
  __syncthreads();

  const int k = g_ksel;
  for (int it = 0; it < k; it++) {
    float best = -INFINITY; int bi = SEQ;
#pragma unroll
    for (int j = 0; j < 4; j++) {
      int i = tid + j * 1024;
      float v = vals[i];
      if (v > best || (v == best && i < bi)) { best = v; bi = i; }
    }
#pragma unroll
    for (int off = 16; off > 0; off >>= 1) {
      float ov = __shfl_down_sync(0xFFFFFFFFu, best, off);
      int oi = __shfl_down_sync(0xFFFFFFFFu, bi, off);
      if (ov > best || (ov == best && oi < bi)) { best = ov; bi = oi; }
    }
    if (l == 0) { wv[w] = best; wi[w] = bi; }
    __syncthreads();
    if (tid < 32) {
      best = wv[tid]; bi = wi[tid];
#pragma unroll
      for (int off = 16; off > 0; off >>= 1) {
        float ov = __shfl_down_sync(0xFFFFFFFFu, best, off);
        int oi = __shfl_down_sync(0xFFFFFFFFu, bi, off);
        if (ov > best || (ov == best && oi < bi)) { best = ov; bi = oi; }
      }
      if (tid == 0) { vals[bi] = -INFINITY; msk[bi] = 1.0f; }
    }
    __syncthreads();
  }
#pragma unroll
  for (int j = 0; j < 4; j++) {
    int i = tid + j * 1024;
    float m = msk[i];
    out_mask[row * SEQ + i] = m;
    g_mask[row * SEQ + i] = m;
  }
}

// ---------------- scatter ----------------
__global__ __launch_bounds__(256)
void scatter_kernel(const float* __restrict__ X, float* __restrict__ out) {
  const int t = blockIdx.x;
  const int tid = threadIdx.x;
  const float m = g_mask[t];
  float4* dst = (float4*)(out + (size_t)t * DDIM);
  if (m != 0.0f) {
    const float4* src = (const float4*)(X + (size_t)t * DDIM);
    dst[tid] = src[tid];
  } else {
    dst[tid] = make_float4(0.0f, 0.0f, 0.0f, 0.0f);
  }
}

// ---------------- launch ----------------
extern "C" void kernel_launch(void* const* d_in, const int* in_sizes, int n_in,
                              void* d_out, int out_size) {
  const float* X  = (const float*)d_in[0];
  const float* W1 = (const float*)d_in[1];
  const float* b1 = (const float*)d_in[2];
  const float* W2 = (const float*)d_in[3];
  const float* b2 = (const float*)d_in[4];
  const float* kl = (const float*)d_in[5];

  float* out = (float*)d_out;
  float* out_mask = out + (size_t)NTOK * DDIM;
  float* out_ek   = out_mask + NTOK;

  uint32_t r1k0, r1k1, r2k0, r2k1;
  tf2x32(0u, 42u, 0u, 0u, &r1k0, &r1k1);
  tf2x32(0u, 42u, 0u, 1u, &r2k0, &r2k1);

  cudaFuncSetAttribute(gemm_logits_kernel,
                       cudaFuncAttributeMaxDynamicSharedMemorySize, DYN_SMEM);

  convX_kernel<<<(NTOK * DDIM / 4) / 256, 256>>>(X);
  convW_kernel<<<dim3(HDIM / 32, DDIM / 32), 256>>>(W1);
  k_select_kernel<<<1, 64>>>(kl, out_ek, r1k0, r1k1);
  gemm_logits_kernel<<<NTOK / BM, 512, DYN_SMEM>>>(b1, W2);
  topk_kernel<<<BATCH, 1024>>>(b2, out_mask, r2k0, r2k1);
  scatter_kernel<<<NTOK, 256>>>(X, out);
}

// round 8
// speedup vs baseline: 5.5566x; 1.9944x over previous
#include <cuda_runtime.h>
#include <cuda_bf16.h>
#include <stdint.h>
#include <math.h>

#define NTOK 32768
#define BATCH 8
#define SEQ 4096
#define DDIM 1024
#define HDIM 2048
#define MAXK 64

#define BM 128
#define BN 256
#define BK 32
#define NCHUNKS (HDIM / BN)          // 8
#define KSTAGES (DDIM / BK)          // 32
#define NSTAGES (NCHUNKS * KSTAGES)  // 256

// smem: 5 stages of [Ahi 10240][Bhi 20480] = 30720 each
#define STAGE_BYTES 30720
#define NPIPE 5
#define B1S_OFF  (NPIPE * STAGE_BYTES)      // 153600
#define W2S_OFF  (B1S_OFF + 8192)
#define RED_OFF  (W2S_OFF + 8192)
#define DYN_SMEM (RED_OFF + 2048)           // 172032

#define MARGIN 0.03f
#define BANDW  0.06f     // 2*MARGIN
#define MAXBAND 64

// ---------------- scratch ----------------
static __device__ float g_logits[NTOK];
static __device__ float g_mask[NTOK];
static __device__ int   g_ksel;
static __device__ __nv_bfloat16 g_Xhi[(size_t)NTOK * DDIM];
static __device__ __nv_bfloat16 g_Whi[(size_t)HDIM * DDIM];  // n-major (transposed)
static __device__ int   g_band_idx[BATCH * MAXBAND];
static __device__ float g_band_partial[BATCH * MAXBAND * 16];
static __device__ int   g_bandcnt[BATCH];
static __device__ int   g_bandsel[BATCH];

// ---------------- PTX helpers ----------------
__device__ __forceinline__ uint32_t smem_u32(const void* p) {
  uint32_t a;
  asm("{ .reg .u64 t; cvta.to.shared.u64 t, %1; cvt.u32.u64 %0, t; }" : "=r"(a) : "l"(p));
  return a;
}
__device__ __forceinline__ void cp16(uint32_t saddr, const void* gaddr) {
  asm volatile("cp.async.cg.shared.global [%0], [%1], 16;" :: "r"(saddr), "l"(gaddr));
}
#define CP_COMMIT() asm volatile("cp.async.commit_group;" ::: "memory")
#define CP_WAIT3()  asm volatile("cp.async.wait_group 3;" ::: "memory")
#define CP_WAIT0()  asm volatile("cp.async.wait_group 0;" ::: "memory")

__device__ __forceinline__ void ldsm4(uint32_t* r, uint32_t addr) {
  asm volatile("ldmatrix.sync.aligned.m8n8.x4.shared.b16 {%0,%1,%2,%3}, [%4];"
               : "=r"(r[0]), "=r"(r[1]), "=r"(r[2]), "=r"(r[3]) : "r"(addr));
}
__device__ __forceinline__ void ldsm_b2(uint32_t (*b)[2], uint32_t addr) {
  uint32_t r[4];
  ldsm4(r, addr);
  b[0][0] = r[0]; b[0][1] = r[2];
  b[1][0] = r[1]; b[1][1] = r[3];
}
__device__ __forceinline__ void mma16816(float* c, const uint32_t* a, const uint32_t* b) {
  asm volatile("mma.sync.aligned.m16n8k16.row.col.f32.bf16.bf16.f32 "
               "{%0,%1,%2,%3}, {%4,%5,%6,%7}, {%8,%9}, {%0,%1,%2,%3};"
               : "+f"(c[0]), "+f"(c[1]), "+f"(c[2]), "+f"(c[3])
               : "r"(a[0]), "r"(a[1]), "r"(a[2]), "r"(a[3]), "r"(b[0]), "r"(b[1]));
}

// ---------------- threefry2x32-20 (JAX) ----------------
__host__ __device__ __forceinline__ void tf2x32(uint32_t k0, uint32_t k1,
                                                uint32_t x0, uint32_t x1,
                                                uint32_t* o0, uint32_t* o1) {
  uint32_t ks2 = k0 ^ k1 ^ 0x1BD11BDAu;
#define ROTL(v, d) (((v) << (d)) | ((v) >> (32 - (d))))
#define RND(r) { x0 += x1; x1 = ROTL(x1, r); x1 ^= x0; }
  x0 += k0; x1 += k1;
  RND(13) RND(15) RND(26) RND(6)
  x0 += k1; x1 += ks2 + 1u;
  RND(17) RND(29) RND(16) RND(24)
  x0 += ks2; x1 += k0 + 2u;
  RND(13) RND(15) RND(26) RND(6)
  x0 += k0; x1 += k1 + 3u;
  RND(17) RND(29) RND(16) RND(24)
  x0 += k1; x1 += ks2 + 4u;
  RND(13) RND(15) RND(26) RND(6)
  x0 += ks2; x1 += k0 + 5u;
#undef RND
#undef ROTL
  *o0 = x0; *o1 = x1;
}
__device__ __forceinline__ float gumbel_at(uint32_t k0, uint32_t k1, uint32_t idx) {
  uint32_t a, b;
  tf2x32(k0, k1, 0u, idx, &a, &b);
  uint32_t bits = a ^ b;
  float u = __uint_as_float((bits >> 9) | 0x3f800000u) - 1.0f;
  u = u + 1e-8f;
  u = fmaxf(1e-8f, u);
  return -logf(-logf(u));
}

// ---------------- conversion kernels (hi only) ----------------
__global__ __launch_bounds__(256) void convX_kernel(const float* __restrict__ X) {
  size_t i = (size_t)blockIdx.x * 256 + threadIdx.x;   // float4 index
  float4 v = ((const float4*)X)[i];
  __nv_bfloat162* H = (__nv_bfloat162*)g_Xhi;
  H[i * 2]     = __nv_bfloat162(__float2bfloat16(v.x), __float2bfloat16(v.y));
  H[i * 2 + 1] = __nv_bfloat162(__float2bfloat16(v.z), __float2bfloat16(v.w));
}

__global__ __launch_bounds__(256) void convW_kernel(const float* __restrict__ W1) {
  __shared__ float s[32][33];
  int n0 = blockIdx.x * 32;
  int k0 = blockIdx.y * 32;
  int tx = threadIdx.x & 31, ty = threadIdx.x >> 5;   // ty 0..7
#pragma unroll
  for (int j = 0; j < 4; j++) {
    int k = k0 + ty + j * 8;
    s[ty + j * 8][tx] = W1[(size_t)k * HDIM + n0 + tx];
  }
  __syncthreads();
#pragma unroll
  for (int j = 0; j < 4; j++) {
    int n = n0 + ty + j * 8;
    g_Whi[(size_t)n * DDIM + k0 + tx] = __float2bfloat16(s[tx][ty + j * 8]);
  }
}

// ---------------- k-select ----------------
__global__ void k_select_kernel(const float* __restrict__ k_logits,
                                float* __restrict__ out_ek,
                                uint32_t r1k0, uint32_t r1k1) {
  __shared__ float z[MAXK];
  int t = threadIdx.x;
  if (t < MAXK) z[t] = k_logits[t] + gumbel_at(r1k0, r1k1, (uint32_t)t);
  __syncthreads();
  if (t == 0) {
    float m = -INFINITY; int am = 0;
    for (int i = 0; i < MAXK; i++) if (z[i] > m) { m = z[i]; am = i; }
    float s = 0.0f, e[MAXK];
    for (int i = 0; i < MAXK; i++) { e[i] = expf(z[i] - m); s += e[i]; }
    float ek = 0.0f;
    for (int i = 0; i < MAXK; i++) ek += (e[i] / s) * (float)(i + 1);
    out_ek[0] = ek;
    g_ksel = am + 1;
  }
}

// ---------------- 1-pass bf16 HMMA GEMM -> approx logits ----------------
__global__ __launch_bounds__(512, 1)
void gemm_logits_kernel(const float* __restrict__ b1, const float* __restrict__ W2) {
  extern __shared__ char smem[];
  const uint32_t sb = smem_u32(smem);
  const int tid = threadIdx.x;
  const int lane = tid & 31;
  const int wid = tid >> 5;
  const int wm = wid & 3;           // 0..3 (m, 32-row slices)
  const int wn = wid >> 2;          // 0..3 (n, 64-col slices)
  const int row0 = blockIdx.x * BM;

  float* b1s = (float*)(smem + B1S_OFF);
  float* w2s = (float*)(smem + W2S_OFF);
  float* red = (float*)(smem + RED_OFF);

  // loader constants: 1536 chunks/stage = 3 per thread (A 512, B 1024)
  const int cr = tid >> 2, ch = tid & 3;
  const char* pXhiB = (const char*)g_Xhi + (((size_t)(row0 + cr)) << 11) + ch * 16;
  const char* pWhiB = (const char*)g_Whi + (((size_t)cr) << 11) + ch * 16;
  const uint32_t sA = (uint32_t)(cr * 80 + ch * 16);

#define ISSUE_STAGE(stgbase, s2) do {                                        \
    const uint32_t _stg = (stgbase);                                         \
    const size_t _ko = (size_t)(((s2) & 31) << 6);                           \
    const size_t _nb = ((size_t)((s2) >> 5)) << 19;                          \
    cp16(_stg + sA,                 pXhiB + _ko);                            \
    cp16(_stg + 10240 + sA,         pWhiB + _nb + _ko);                      \
    cp16(_stg + 20480 + sA,         pWhiB + _nb + (128ull << 11) + _ko);     \
  } while (0)

  // prefetch 4 stages
#pragma unroll
  for (int p = 0; p < 4; p++) {
    ISSUE_STAGE(sb + p * STAGE_BYTES, p);
    CP_COMMIT();
  }

  // stage b1/W2 (published by loop barriers before first epilogue at s=31)
#pragma unroll
  for (int i = 0; i < 4; i++) {
    b1s[tid + i * 512] = b1[tid + i * 512];
    w2s[tid + i * 512] = W2[tid + i * 512];
  }

  float C[2][8][4];
#pragma unroll
  for (int mi = 0; mi < 2; mi++)
#pragma unroll
    for (int ni = 0; ni < 8; ni++)
#pragma unroll
      for (int j = 0; j < 4; j++) C[mi][ni][j] = 0.0f;
  float lacc[4] = {0.0f, 0.0f, 0.0f, 0.0f};

  const int lr = lane & 15, lh = lane >> 4;
  const uint32_t aOff = (uint32_t)((wm * 32 + lr) * 80 + lh * 16);
  const uint32_t bOff = (uint32_t)(10240 + (wn * 64 + lr) * 80 + lh * 16);

  int buf = 0;
  for (int s = 0; s < NSTAGES; s++) {
    if (s + 4 < NSTAGES) CP_WAIT3(); else CP_WAIT0();
    __syncthreads();   // publish buf s; certify compute(s-1) done
    if (s + 4 < NSTAGES) {
      int b4 = buf + 4; if (b4 >= NPIPE) b4 -= NPIPE;
      ISSUE_STAGE(sb + b4 * STAGE_BYTES, s + 4);
      CP_COMMIT();
    }

    const uint32_t stg = sb + buf * STAGE_BYTES;
    const uint32_t aB = stg + aOff;
    const uint32_t bB = stg + bOff;
#pragma unroll
    for (int k16 = 0; k16 < 2; k16++) {
      uint32_t ah[2][4], bb0[4][2], bb1[4][2];
      const uint32_t kofs = k16 * 32;
      ldsm4(ah[0], aB + kofs);
      ldsm4(ah[1], aB + 16 * 80 + kofs);
      ldsm_b2(bb0 + 0, bB + kofs);
      ldsm_b2(bb0 + 2, bB + 16 * 80 + kofs);
      ldsm_b2(bb1 + 0, bB + 2 * (16 * 80) + kofs);
      ldsm_b2(bb1 + 2, bB + 3 * (16 * 80) + kofs);
#pragma unroll
      for (int mi = 0; mi < 2; mi++)
#pragma unroll
        for (int ni = 0; ni < 4; ni++) mma16816(C[mi][ni], ah[mi], bb0[ni]);
#pragma unroll
      for (int mi = 0; mi < 2; mi++)
#pragma unroll
        for (int ni = 0; ni < 4; ni++) mma16816(C[mi][ni + 4], ah[mi], bb1[ni]);
    }

    if ((s & 31) == 31) {
      const int colbase = (s >> 5) * BN + wn * 64 + (lane & 3) * 2;
#pragma unroll
      for (int ni = 0; ni < 8; ni++) {
        const int c0 = colbase + ni * 8;
        const float b10 = b1s[c0], b11 = b1s[c0 + 1];
        const float w20 = w2s[c0], w21 = w2s[c0 + 1];
#pragma unroll
        for (int mi = 0; mi < 2; mi++) {
          lacc[mi * 2 + 0] += fmaxf(C[mi][ni][0] + b10, 0.0f) * w20
                            + fmaxf(C[mi][ni][1] + b11, 0.0f) * w21;
          lacc[mi * 2 + 1] += fmaxf(C[mi][ni][2] + b10, 0.0f) * w20
                            + fmaxf(C[mi][ni][3] + b11, 0.0f) * w21;
          C[mi][ni][0] = 0.0f; C[mi][ni][1] = 0.0f;
          C[mi][ni][2] = 0.0f; C[mi][ni][3] = 0.0f;
        }
      }
    }
    buf++; if (buf == NPIPE) buf = 0;
  }

#pragma unroll
  for (int j = 0; j < 4; j++) {
    lacc[j] += __shfl_xor_sync(0xFFFFFFFFu, lacc[j], 1);
    lacc[j] += __shfl_xor_sync(0xFFFFFFFFu, lacc[j], 2);
  }
  __syncthreads();
  if ((lane & 3) == 0) {
    const int r = lane >> 2;
    red[wn * 128 + wm * 32 + r]      = lacc[0];
    red[wn * 128 + wm * 32 + 8 + r]  = lacc[1];
    red[wn * 128 + wm * 32 + 16 + r] = lacc[2];
    red[wn * 128 + wm * 32 + 24 + r] = lacc[3];
  }
  __syncthreads();
  if (tid < BM)
    g_logits[row0 + tid] = (red[tid] + red[128 + tid]) + (red[256 + tid] + red[384 + tid]);
}

// ---------------- top-k on approx + band extraction ----------------
__global__ __launch_bounds__(1024)
void topk_kernel(float* __restrict__ out_mask, uint32_t r2k0, uint32_t r2k1) {
  __shared__ float vals[SEQ];
  __shared__ float orig[SEQ];
  __shared__ unsigned char msk[SEQ];
  __shared__ float wv[32];
  __shared__ int wi[32];
  __shared__ float sAk;
  __shared__ int scnt, scsel;
  const int row = blockIdx.x;
  const int tid = threadIdx.x;
  const int w = tid >> 5, l = tid & 31;

#pragma unroll
  for (int j = 0; j < 4; j++) {
    int i = tid + j * 1024;
    uint32_t idx = (uint32_t)(row * SEQ + i);
    float v = g_logits[idx] + gumbel_at(r2k0, r2k1, idx);
    vals[i] = v; orig[i] = v; msk[i] = 0;
  }
  if (tid == 0) { scnt = 0; scsel = 0; }
  __syncthreads();

  const int k = g_ksel;
  for (int it = 0; it < k; it++) {
    float best = -INFINITY; int bi = SEQ;
#pragma unroll
    for (int j = 0; j < 4; j++) {
      int i = tid + j * 1024;
      float v = vals[i];
      if (v > best || (v == best && i < bi)) { best = v; bi = i; }
    }
#pragma unroll
    for (int off = 16; off > 0; off >>= 1) {
      float ov = __shfl_down_sync(0xFFFFFFFFu, best, off);
      int oi = __shfl_down_sync(0xFFFFFFFFu, bi, off);
      if (ov > best || (ov == best && oi < bi)) { best = ov; bi = oi; }
    }
    if (l == 0) { wv[w] = best; wi[w] = bi; }
    __syncthreads();
    if (tid < 32) {
      best = wv[tid]; bi = wi[tid];
#pragma unroll
      for (int off = 16; off > 0; off >>= 1) {
        float ov = __shfl_down_sync(0xFFFFFFFFu, best, off);
        int oi = __shfl_down_sync(0xFFFFFFFFu, bi, off);
        if (ov > best || (ov == best && oi < bi)) { best = ov; bi = oi; }
      }
      if (tid == 0) {
        vals[bi] = -INFINITY; msk[bi] = 1;
        if (it == k - 1) sAk = best;
      }
    }
    __syncthreads();
  }

  // provisional masks + band capture
#pragma unroll
  for (int j = 0; j < 4; j++) {
    int i = tid + j * 1024;
    float m = (float)msk[i];
    out_mask[row * SEQ + i] = m;
    g_mask[row * SEQ + i] = m;
    if (fabsf(orig[i] - sAk) <= BANDW) {
      int p = atomicAdd(&scnt, 1);
      if (p < MAXBAND) g_band_idx[row * MAXBAND + p] = i;
      if (msk[i]) atomicAdd(&scsel, 1);
    }
  }
  __syncthreads();
  if (tid == 0) {
    g_bandcnt[row] = scnt < MAXBAND ? scnt : MAXBAND;
    g_bandsel[row] = scsel;
  }
}

// ---------------- refine: exact fp32 logits for band tokens ----------------
// grid (16 jchunks, 8 rows, 4 cand-tiles), block 256
__global__ __launch_bounds__(256)
void refine_kernel(const float* __restrict__ X, const float* __restrict__ W1,
                   const float* __restrict__ b1, const float* __restrict__ W2) {
  const int jc = blockIdx.x, row = blockIdx.y, c0 = blockIdx.z * 16;
  const int cnt = g_bandcnt[row];
  if (c0 >= cnt) return;
  const int tid = threadIdx.x;
  const int tc = tid & 15, tj = tid >> 4;

  __shared__ int stok[16];
  __shared__ float Xs[16][33];
  __shared__ float Ws[32][132];
  __shared__ float part[16][17];

  if (tid < 16)
    stok[tid] = (c0 + tid < cnt) ? row * SEQ + g_band_idx[row * MAXBAND + c0 + tid]
                                 : row * SEQ;
  __syncthreads();

  float acc[8];
#pragma unroll
  for (int u = 0; u < 8; u++) acc[u] = 0.0f;

  for (int k0 = 0; k0 < DDIM; k0 += 32) {
#pragma unroll
    for (int p = 0; p < 2; p++) {
      int e = tid + p * 256;
      int c = e >> 5, kk = e & 31;
      Xs[c][kk] = X[(size_t)stok[c] * DDIM + k0 + kk];
    }
#pragma unroll
    for (int q = 0; q < 16; q++) {
      int f = tid + q * 256;
      int kk = f >> 7, jj = f & 127;
      Ws[kk][jj] = W1[(size_t)(k0 + kk) * HDIM + jc * 128 + jj];
    }
    __syncthreads();
#pragma unroll
    for (int kk = 0; kk < 32; kk++) {
      float x = Xs[tc][kk];
      const float4* wrow = (const float4*)&Ws[kk][tj * 8];
      float4 w0 = wrow[0], w1 = wrow[1];
      acc[0] = fmaf(x, w0.x, acc[0]); acc[1] = fmaf(x, w0.y, acc[1]);
      acc[2] = fmaf(x, w0.z, acc[2]); acc[3] = fmaf(x, w0.w, acc[3]);
      acc[4] = fmaf(x, w1.x, acc[4]); acc[5] = fmaf(x, w1.y, acc[5]);
      acc[6] = fmaf(x, w1.z, acc[6]); acc[7] = fmaf(x, w1.w, acc[7]);
    }
    __syncthreads();
  }

  float contrib = 0.0f;
#pragma unroll
  for (int u = 0; u < 8; u++) {
    int j = jc * 128 + tj * 8 + u;
    float h = acc[u] + b1[j];
    contrib += fmaxf(h, 0.0f) * W2[j];
  }
  part[tj][tc] = contrib;
  __syncthreads();
  if (tid < 16) {
    float s = 0.0f;
#pragma unroll
    for (int t = 0; t < 16; t++) s += part[t][tid];
    if (c0 + tid < cnt)
      g_band_partial[(row * MAXBAND + c0 + tid) * 16 + jc] = s;
  }
}

// ---------------- fixup: re-rank band by exact values ----------------
__global__ __launch_bounds__(64)
void fixup_kernel(float* __restrict__ out_mask, uint32_t r2k0, uint32_t r2k1) {
  const int row = blockIdx.x, t = threadIdx.x;
  const int cnt = g_bandcnt[row], csel = g_bandsel[row];
  __shared__ float sv[64], svv[64];
  __shared__ int si[64];

  float v = -INFINITY; int idx = -1;
  if (t < cnt) {
    idx = g_band_idx[row * MAXBAND + t];
    float s = 0.0f;
#pragma unroll
    for (int c = 0; c < 16; c++) s += g_band_partial[(row * MAXBAND + t) * 16 + c];
    v = s + gumbel_at(r2k0, r2k1, (uint32_t)(row * SEQ + idx));
  }
  svv[t] = v;
  __syncthreads();

  int chosen = 0;
  for (int it = 0; it < csel; it++) {
    sv[t] = svv[t]; si[t] = t;
    __syncthreads();
    for (int off = 32; off > 0; off >>= 1) {
      if (t < off) {
        if (sv[t + off] > sv[t] || (sv[t + off] == sv[t] && si[t + off] < si[t])) {
          sv[t] = sv[t + off]; si[t] = si[t + off];
        }
      }
      __syncthreads();
    }
    if (t == si[0]) { chosen = 1; svv[t] = -INFINITY; }
    __syncthreads();
  }

  if (t < cnt) {
    float m = (float)chosen;
    out_mask[row * SEQ + idx] = m;
    g_mask[row * SEQ + idx] = m;
  }
}

// ---------------- scatter ----------------
__global__ __launch_bounds__(256)
void scatter_kernel(const float* __restrict__ X, float* __restrict__ out) {
  const int t = blockIdx.x;
  const int tid = threadIdx.x;
  const float m = g_mask[t];
  float4* dst = (float4*)(out + (size_t)t * DDIM);
  if (m != 0.0f) {
    const float4* src = (const float4*)(X + (size_t)t * DDIM);
    dst[tid] = src[tid];
  } else {
    dst[tid] = make_float4(0.0f, 0.0f, 0.0f, 0.0f);
  }
}

// ---------------- launch ----------------
extern "C" void kernel_launch(void* const* d_in, const int* in_sizes, int n_in,
                              void* d_out, int out_size) {
  const float* X  = (const float*)d_in[0];
  const float* W1 = (const float*)d_in[1];
  const float* b1 = (const float*)d_in[2];
  const float* W2 = (const float*)d_in[3];
  const float* kl = (const float*)d_in[5];

  float* out = (float*)d_out;
  float* out_mask = out + (size_t)NTOK * DDIM;
  float* out_ek   = out_mask + NTOK;

  uint32_t r1k0, r1k1, r2k0, r2k1;
  tf2x32(0u, 42u, 0u, 0u, &r1k0, &r1k1);
  tf2x32(0u, 42u, 0u, 1u, &r2k0, &r2k1);

  cudaFuncSetAttribute(gemm_logits_kernel,
                       cudaFuncAttributeMaxDynamicSharedMemorySize, DYN_SMEM);

  convX_kernel<<<(NTOK * DDIM / 4) / 256, 256>>>(X);
  convW_kernel<<<dim3(HDIM / 32, DDIM / 32), 256>>>(W1);
  k_select_kernel<<<1, 64>>>(kl, out_ek, r1k0, r1k1);
  gemm_logits_kernel<<<NTOK / BM, 512, DYN_SMEM>>>(b1, W2);
  topk_kernel<<<BATCH, 1024>>>(out_mask, r2k0, r2k1);
  refine_kernel<<<dim3(16, BATCH, 4), 256>>>(X, W1, b1, W2);
  fixup_kernel<<<BATCH, 64>>>(out_mask, r2k0, r2k1);
  scatter_kernel<<<NTOK, 256>>>(X, out);
}